// round 1
// baseline (speedup 1.0000x reference)
#include <cuda_runtime.h>
#include <cuda_bf16.h>
#include <math.h>

#define B_ 4
#define T_ 1024
#define C_ 1024
#define H_ 16
#define D_ 64

// ---------------- scratch (device globals; no allocations allowed) ----------
__device__ float g_qkv[(size_t)B_ * T_ * 3 * C_];          // 48 MB
__device__ float g_Qp[(size_t)B_ * H_ * T_ * D_];          // 16 MB
__device__ float g_Kp[(size_t)B_ * H_ * T_ * D_];          // 16 MB
__device__ float g_V [(size_t)B_ * H_ * T_ * D_];          // 16 MB
__device__ float g_Y [(size_t)B_ * T_ * C_];               // 16 MB
__device__ float g_spike[B_ * T_];

// ---------------- spike gate -------------------------------------------------
__global__ void spike_kernel(const float* __restrict__ x,
                             const float* __restrict__ w_sur,
                             const float* __restrict__ b_sur,
                             const float* __restrict__ threshold) {
    int row = blockIdx.x * (blockDim.x / 32) + (threadIdx.x >> 5);   // 0..B*T-1
    int lane = threadIdx.x & 31;
    const float* xr = x + (size_t)row * C_;
    float s = 0.f;
    #pragma unroll 4
    for (int i = lane; i < C_; i += 32) s += xr[i] * w_sur[i];
    #pragma unroll
    for (int m = 16; m; m >>= 1) s += __shfl_xor_sync(0xffffffffu, s, m);
    if (lane == 0) {
        float z = s + b_sur[0];
        float imp = 1.f / (1.f + expf(-z));
        g_spike[row] = (imp > threshold[0]) ? 1.f : 0.f;
    }
}

// ---------------- SGEMM: C = A(MxK) @ B(KxN) + bias -------------------------
#define BM 128
#define BN 128
#define BKK 16
#define TM 8
#define TN 8

__global__ __launch_bounds__(256) void sgemm_bias_kernel(
    int M, int N, int K,
    const float* __restrict__ A, const float* __restrict__ Bm,
    const float* __restrict__ bias, float* __restrict__ C)
{
    __shared__ float As[BKK][BM + 4];
    __shared__ float Bs[BKK][BN];

    int bx = blockIdx.x;   // N tile
    int by = blockIdx.y;   // M tile
    int tid = threadIdx.x;
    int tr = tid / 16, tc = tid % 16;

    const float* Ab = A + (size_t)by * BM * K;
    const float* Bb = Bm + (size_t)bx * BN;

    float acc[TM][TN];
    #pragma unroll
    for (int i = 0; i < TM; i++)
        #pragma unroll
        for (int j = 0; j < TN; j++) acc[i][j] = 0.f;

    for (int k0 = 0; k0 < K; k0 += BKK) {
        #pragma unroll
        for (int it = 0; it < 2; it++) {
            int id = tid + it * 256;
            int row = id >> 2;            // 0..127
            int c4  = id & 3;             // 0..3
            float4 v = *(const float4*)(Ab + (size_t)row * K + k0 + c4 * 4);
            As[c4 * 4 + 0][row] = v.x;
            As[c4 * 4 + 1][row] = v.y;
            As[c4 * 4 + 2][row] = v.z;
            As[c4 * 4 + 3][row] = v.w;
        }
        #pragma unroll
        for (int it = 0; it < 2; it++) {
            int id = tid + it * 256;
            int row = id >> 5;            // 0..15
            int c4  = id & 31;            // 0..31
            *(float4*)&Bs[row][c4 * 4] =
                *(const float4*)(Bb + (size_t)(k0 + row) * N + c4 * 4);
        }
        __syncthreads();
        #pragma unroll
        for (int k = 0; k < BKK; k++) {
            float a[TM], b[TN];
            #pragma unroll
            for (int i = 0; i < TM; i++) a[i] = As[k][tr * TM + i];
            #pragma unroll
            for (int j = 0; j < TN; j++) b[j] = Bs[k][tc * TN + j];
            #pragma unroll
            for (int i = 0; i < TM; i++)
                #pragma unroll
                for (int j = 0; j < TN; j++)
                    acc[i][j] += a[i] * b[j];
        }
        __syncthreads();
    }

    #pragma unroll
    for (int i = 0; i < TM; i++) {
        int row = by * BM + tr * TM + i;
        #pragma unroll
        for (int j = 0; j < TN; j += 4) {
            int col = bx * BN + tc * TN + j;
            float4 v;
            v.x = acc[i][j + 0] + bias[col + 0];
            v.y = acc[i][j + 1] + bias[col + 1];
            v.z = acc[i][j + 2] + bias[col + 2];
            v.w = acc[i][j + 3] + bias[col + 3];
            *(float4*)(C + (size_t)row * N + col) = v;
        }
    }
}

// ---------------- Lorentz expmap transform ----------------------------------
// Q'[0]=cosh(n), Q'[d]= (sinh(n)/n) q_d ; K'[0]=cosh(n), K'[d]= -(sinh(n)/n) k_d
__global__ void transform_kernel() {
    int wid = blockIdx.x * (blockDim.x / 32) + (threadIdx.x >> 5);  // 0..B*H*T-1
    int lane = threadIdx.x & 31;
    int t = wid % T_;
    int h = (wid / T_) % H_;
    int b = wid / (T_ * H_);
    const float* base = g_qkv + ((size_t)(b * T_ + t)) * (3 * C_);
    size_t outoff = ((size_t)(b * H_ + h) * T_ + t) * D_;

    // ---- Q ----
    {
        const float* u = base + 0 * C_ + h * D_;
        float lo = u[lane], hi = u[lane + 32];
        float ss = lo * lo + hi * hi;
        #pragma unroll
        for (int m = 16; m; m >>= 1) ss += __shfl_xor_sync(0xffffffffu, ss, m);
        float u0 = __shfl_sync(0xffffffffu, lo, 0);
        float mink = ss - 2.f * u0 * u0;
        float n = sqrtf(fmaxf(mink, 1e-8f));
        float tme = coshf(n);
        float coef = sinhf(n) / n;
        g_Qp[outoff + lane]      = (lane == 0) ? tme : coef * lo;
        g_Qp[outoff + lane + 32] = coef * hi;
    }
    // ---- K ----
    {
        const float* u = base + 1 * C_ + h * D_;
        float lo = u[lane], hi = u[lane + 32];
        float ss = lo * lo + hi * hi;
        #pragma unroll
        for (int m = 16; m; m >>= 1) ss += __shfl_xor_sync(0xffffffffu, ss, m);
        float u0 = __shfl_sync(0xffffffffu, lo, 0);
        float mink = ss - 2.f * u0 * u0;
        float n = sqrtf(fmaxf(mink, 1e-8f));
        float tme = coshf(n);
        float coef = sinhf(n) / n;
        g_Kp[outoff + lane]      = (lane == 0) ? tme : -coef * lo;
        g_Kp[outoff + lane + 32] = -coef * hi;
    }
    // ---- V ----
    {
        const float* u = base + 2 * C_ + h * D_;
        g_V[outoff + lane]      = u[lane];
        g_V[outoff + lane + 32] = u[lane + 32];
    }
}

// ---------------- flash attention with Lorentz score transform --------------
// score = -acosh(max(Q'.K', 1+1e-7))^2 / 8, causal, softmax, *spike, @V
#define APAD 65
#define ATTN_SMEM (4 * 64 * APAD * 4)

__global__ __launch_bounds__(256) void attn_kernel() {
    extern __shared__ float sm[];
    float* Qs = sm;                    // [64][65]
    float* Ks = sm + 64 * APAD;        // [64][65]
    float* Vs = sm + 2 * 64 * APAD;    // [64][65]
    float* Ps = sm + 3 * 64 * APAD;    // [64][65]

    int ti = blockIdx.x;       // i tile (0..15)
    int h  = blockIdx.y;
    int b  = blockIdx.z;
    int bh = b * H_ + h;
    int tid = threadIdx.x;
    int tr = tid / 16;         // 0..15 -> 4 rows each
    int tc = tid % 16;         // 0..15 -> 4 cols each
    int i0 = ti * 64;

    const float* Qg = g_Qp + ((size_t)bh * T_ + i0) * D_;

    // load Q tile
    #pragma unroll
    for (int it = 0; it < 4; it++) {
        int id = tid + it * 256;
        int r = id >> 4, c4 = (id & 15) * 4;
        float4 v = *(const float4*)(Qg + (size_t)r * D_ + c4);
        Qs[r * APAD + c4 + 0] = v.x;
        Qs[r * APAD + c4 + 1] = v.y;
        Qs[r * APAD + c4 + 2] = v.z;
        Qs[r * APAD + c4 + 3] = v.w;
    }

    float m_r[4], l_r[4], O[4][4];
    #pragma unroll
    for (int i = 0; i < 4; i++) {
        m_r[i] = -1e30f; l_r[i] = 0.f;
        #pragma unroll
        for (int j = 0; j < 4; j++) O[i][j] = 0.f;
    }
    __syncthreads();

    for (int tj = 0; tj <= ti; tj++) {
        int j0 = tj * 64;
        const float* Kg = g_Kp + ((size_t)bh * T_ + j0) * D_;
        const float* Vg = g_V  + ((size_t)bh * T_ + j0) * D_;
        #pragma unroll
        for (int it = 0; it < 4; it++) {
            int id = tid + it * 256;
            int r = id >> 4, c4 = (id & 15) * 4;
            float4 v = *(const float4*)(Kg + (size_t)r * D_ + c4);
            Ks[r * APAD + c4 + 0] = v.x;
            Ks[r * APAD + c4 + 1] = v.y;
            Ks[r * APAD + c4 + 2] = v.z;
            Ks[r * APAD + c4 + 3] = v.w;
            float4 w = *(const float4*)(Vg + (size_t)r * D_ + c4);
            Vs[r * APAD + c4 + 0] = w.x;
            Vs[r * APAD + c4 + 1] = w.y;
            Vs[r * APAD + c4 + 2] = w.z;
            Vs[r * APAD + c4 + 3] = w.w;
        }
        __syncthreads();

        // S = Q' K'^T  (4x4 per thread)
        float acc[4][4];
        #pragma unroll
        for (int i = 0; i < 4; i++)
            #pragma unroll
            for (int j = 0; j < 4; j++) acc[i][j] = 0.f;
        #pragma unroll 8
        for (int d = 0; d < 64; d++) {
            float a[4], bb[4];
            #pragma unroll
            for (int i = 0; i < 4; i++) a[i]  = Qs[(tr * 4 + i) * APAD + d];
            #pragma unroll
            for (int j = 0; j < 4; j++) bb[j] = Ks[(tc * 4 + j) * APAD + d];
            #pragma unroll
            for (int i = 0; i < 4; i++)
                #pragma unroll
                for (int j = 0; j < 4; j++)
                    acc[i][j] += a[i] * bb[j];
        }

        // transform to scores + causal mask on diagonal tile
        bool diag = (tj == ti);
        #pragma unroll
        for (int i = 0; i < 4; i++) {
            int rg = tr * 4 + i;
            #pragma unroll
            for (int j = 0; j < 4; j++) {
                int cg = tc * 4 + j;
                float xni = fmaxf(acc[i][j], 1.0f + 1e-7f);
                float dd = acoshf(xni);
                float sc = -dd * dd * 0.125f;
                if (diag && cg > rg) sc = -1e30f;
                acc[i][j] = sc;
            }
        }

        // online softmax
        #pragma unroll
        for (int i = 0; i < 4; i++) {
            float mx = acc[i][0];
            #pragma unroll
            for (int j = 1; j < 4; j++) mx = fmaxf(mx, acc[i][j]);
            #pragma unroll
            for (int m = 8; m; m >>= 1)
                mx = fmaxf(mx, __shfl_xor_sync(0xffffffffu, mx, m));
            float mnew = fmaxf(m_r[i], mx);
            float scale = expf(m_r[i] - mnew);
            l_r[i] *= scale;
            #pragma unroll
            for (int j = 0; j < 4; j++) O[i][j] *= scale;
            float rs = 0.f;
            #pragma unroll
            for (int j = 0; j < 4; j++) {
                float p = expf(acc[i][j] - mnew);
                acc[i][j] = p;
                rs += p;
            }
            #pragma unroll
            for (int m = 8; m; m >>= 1)
                rs += __shfl_xor_sync(0xffffffffu, rs, m);
            l_r[i] += rs;
            m_r[i] = mnew;
        }

        // write P, then PV
        #pragma unroll
        for (int i = 0; i < 4; i++)
            #pragma unroll
            for (int j = 0; j < 4; j++)
                Ps[(tr * 4 + i) * APAD + tc * 4 + j] = acc[i][j];
        __syncthreads();

        #pragma unroll 4
        for (int j = 0; j < 64; j++) {
            float p[4], v[4];
            #pragma unroll
            for (int i = 0; i < 4; i++) p[i] = Ps[(tr * 4 + i) * APAD + j];
            #pragma unroll
            for (int jj = 0; jj < 4; jj++) v[jj] = Vs[j * APAD + tc * 4 + jj];
            #pragma unroll
            for (int i = 0; i < 4; i++)
                #pragma unroll
                for (int jj = 0; jj < 4; jj++)
                    O[i][jj] += p[i] * v[jj];
        }
        __syncthreads();
    }

    // epilogue: /l, *spike, write Y (B,T,H*D)
    #pragma unroll
    for (int i = 0; i < 4; i++) {
        int r = i0 + tr * 4 + i;
        float inv = g_spike[b * T_ + r] / l_r[i];
        float* yp = g_Y + ((size_t)(b * T_ + r)) * C_ + h * D_ + tc * 4;
        float4 v;
        v.x = O[i][0] * inv;
        v.y = O[i][1] * inv;
        v.z = O[i][2] * inv;
        v.w = O[i][3] * inv;
        *(float4*)yp = v;
    }
}

// ---------------- wrappers needing scratch symbol addresses -----------------
__global__ void dummy_noop() {}

extern "C" void kernel_launch(void* const* d_in, const int* in_sizes, int n_in,
                              void* d_out, int out_size) {
    const float* x      = (const float*)d_in[0];
    const float* W_qkv  = (const float*)d_in[1];
    const float* b_qkv  = (const float*)d_in[2];
    const float* W_out  = (const float*)d_in[3];
    const float* b_out  = (const float*)d_in[4];
    const float* w_sur  = (const float*)d_in[5];
    const float* b_sur  = (const float*)d_in[6];
    const float* thresh = (const float*)d_in[7];
    float* out = (float*)d_out;

    // device scratch pointers
    float *p_qkv, *p_Y;
    cudaGetSymbolAddress((void**)&p_qkv, g_qkv);
    cudaGetSymbolAddress((void**)&p_Y,   g_Y);

    const int M = B_ * T_;   // 4096

    // 1. spike gate
    spike_kernel<<<M / 8, 256>>>(x, w_sur, b_sur, thresh);

    // 2. QKV GEMM: (4096 x 1024) @ (1024 x 3072) + b
    sgemm_bias_kernel<<<dim3(3 * C_ / BN, M / BM), 256>>>(
        M, 3 * C_, C_, x, W_qkv, b_qkv, p_qkv);

    // 3. Lorentz transform -> Q', K', V  (one warp per (b,h,t))
    transform_kernel<<<(B_ * H_ * T_) / 8, 256>>>();

    // 4. flash attention
    cudaFuncSetAttribute(attn_kernel,
                         cudaFuncAttributeMaxDynamicSharedMemorySize, ATTN_SMEM);
    attn_kernel<<<dim3(T_ / 64, H_, B_), 256, ATTN_SMEM>>>();

    // 5. out projection: (4096 x 1024) @ (1024 x 1024) + b -> d_out
    sgemm_bias_kernel<<<dim3(C_ / BN, M / BM), 256>>>(
        M, C_, C_, p_Y, W_out, b_out, out);
}

// round 4
// speedup vs baseline: 1.5934x; 1.5934x over previous
#include <cuda_runtime.h>
#include <cuda_bf16.h>
#include <math.h>
#include <stdint.h>

#define B_ 4
#define T_ 1024
#define C_ 1024
#define H_ 16
#define D_ 64

// ---------------- scratch (device globals; no allocations allowed) ----------
__device__ float g_qkv[(size_t)B_ * T_ * 3 * C_];          // 48 MB
__device__ float g_Qp[(size_t)B_ * H_ * T_ * D_];          // 16 MB
__device__ float g_Kp[(size_t)B_ * H_ * T_ * D_];          // 16 MB
__device__ float g_V [(size_t)B_ * H_ * T_ * D_];          // 16 MB
__device__ float g_Y [(size_t)B_ * T_ * C_];               // 16 MB
__device__ float g_spike[B_ * T_];

// bf16 hi/lo split operands for tensor-core GEMMs
__device__ __nv_bfloat16 g_xhi[(size_t)B_ * T_ * C_];
__device__ __nv_bfloat16 g_xlo[(size_t)B_ * T_ * C_];
__device__ __nv_bfloat16 g_Wqt_hi[(size_t)3 * C_ * C_];    // W_qkv^T [N,K]
__device__ __nv_bfloat16 g_Wqt_lo[(size_t)3 * C_ * C_];
__device__ __nv_bfloat16 g_Yhi[(size_t)B_ * T_ * C_];
__device__ __nv_bfloat16 g_Ylo[(size_t)B_ * T_ * C_];
__device__ __nv_bfloat16 g_Wot_hi[(size_t)C_ * C_];        // W_out^T [N,K]
__device__ __nv_bfloat16 g_Wot_lo[(size_t)C_ * C_];

// ======================= generic-PTX helpers (no 'a' features) ==============
__device__ __forceinline__ uint32_t smem_u32(const void* p) {
    uint32_t a;
    asm("{ .reg .u64 t; cvta.to.shared.u64 t, %1; cvt.u32.u64 %0, t; }"
        : "=r"(a) : "l"(p));
    return a;
}
#define CP16(saddr, gaddr) \
    asm volatile("cp.async.cg.shared.global [%0], [%1], 16;" \
                 :: "r"(saddr), "l"(gaddr))
#define CP_COMMIT() asm volatile("cp.async.commit_group;" ::: "memory")
#define CP_WAIT1()  asm volatile("cp.async.wait_group 1;" ::: "memory")
#define CP_WAIT0()  asm volatile("cp.async.wait_group 0;" ::: "memory")

#define LDSM_X4(r0, r1, r2, r3, addr) \
    asm volatile("ldmatrix.sync.aligned.m8n8.x4.shared.b16 {%0,%1,%2,%3}, [%4];" \
                 : "=r"(r0), "=r"(r1), "=r"(r2), "=r"(r3) : "r"(addr))

#define MMA_BF16(d, a, b0, b1) \
    asm volatile("mma.sync.aligned.m16n8k16.row.col.f32.bf16.bf16.f32 " \
                 "{%0,%1,%2,%3}, {%4,%5,%6,%7}, {%8,%9}, {%0,%1,%2,%3};" \
                 : "+f"((d)[0]), "+f"((d)[1]), "+f"((d)[2]), "+f"((d)[3]) \
                 : "r"((a)[0]), "r"((a)[1]), "r"((a)[2]), "r"((a)[3]), \
                   "r"(b0), "r"(b1))

// ---------------- spike gate -------------------------------------------------
__global__ void spike_kernel(const float* __restrict__ x,
                             const float* __restrict__ w_sur,
                             const float* __restrict__ b_sur,
                             const float* __restrict__ threshold) {
    int row = blockIdx.x * (blockDim.x / 32) + (threadIdx.x >> 5);
    int lane = threadIdx.x & 31;
    const float* xr = x + (size_t)row * C_;
    float s = 0.f;
    #pragma unroll 4
    for (int i = lane; i < C_; i += 32) s += xr[i] * w_sur[i];
    #pragma unroll
    for (int m = 16; m; m >>= 1) s += __shfl_xor_sync(0xffffffffu, s, m);
    if (lane == 0) {
        float z = s + b_sur[0];
        float imp = 1.f / (1.f + expf(-z));
        g_spike[row] = (imp > threshold[0]) ? 1.f : 0.f;
    }
}

// ---------------- fp32 -> bf16 hi/lo split (elementwise) --------------------
__global__ void split_kernel(const float* __restrict__ src,
                             __nv_bfloat16* __restrict__ hi,
                             __nv_bfloat16* __restrict__ lo, int n4) {
    int i = blockIdx.x * blockDim.x + threadIdx.x;
    if (i >= n4) return;
    float4 v = *(const float4*)(src + (size_t)i * 4);
    __nv_bfloat16 h0 = __float2bfloat16(v.x);
    __nv_bfloat16 h1 = __float2bfloat16(v.y);
    __nv_bfloat16 h2 = __float2bfloat16(v.z);
    __nv_bfloat16 h3 = __float2bfloat16(v.w);
    __nv_bfloat16 l0 = __float2bfloat16(v.x - __bfloat162float(h0));
    __nv_bfloat16 l1 = __float2bfloat16(v.y - __bfloat162float(h1));
    __nv_bfloat16 l2 = __float2bfloat16(v.z - __bfloat162float(h2));
    __nv_bfloat16 l3 = __float2bfloat16(v.w - __bfloat162float(h3));
    __nv_bfloat162* hp = (__nv_bfloat162*)(hi + (size_t)i * 4);
    __nv_bfloat162* lp = (__nv_bfloat162*)(lo + (size_t)i * 4);
    hp[0] = __nv_bfloat162(h0, h1); hp[1] = __nv_bfloat162(h2, h3);
    lp[0] = __nv_bfloat162(l0, l1); lp[1] = __nv_bfloat162(l2, l3);
}

// ---------------- W[K,N] -> W^T[N,K] bf16 hi/lo split -----------------------
__global__ void transpose_split_kernel(const float* __restrict__ W,
                                       __nv_bfloat16* __restrict__ Thi,
                                       __nv_bfloat16* __restrict__ Tlo,
                                       int K, int N) {
    __shared__ float tile[32][33];
    int k0 = blockIdx.y * 32, n0 = blockIdx.x * 32;
    int tx = threadIdx.x, ty = threadIdx.y;    // 32 x 8
    #pragma unroll
    for (int j = 0; j < 32; j += 8)
        tile[ty + j][tx] = W[(size_t)(k0 + ty + j) * N + n0 + tx];
    __syncthreads();
    #pragma unroll
    for (int j = 0; j < 32; j += 8) {
        float v = tile[tx][ty + j];
        __nv_bfloat16 h = __float2bfloat16(v);
        __nv_bfloat16 l = __float2bfloat16(v - __bfloat162float(h));
        Thi[(size_t)(n0 + ty + j) * K + k0 + tx] = h;
        Tlo[(size_t)(n0 + ty + j) * K + k0 + tx] = l;
    }
}

// ---------------- mma.sync bf16x3 GEMM: C = A @ B^T + bias ------------------
// A[M,K] hi/lo bf16 (K-major), B[N,K] hi/lo bf16 (K-major).
// CTA 128x128, BK=32, 8 warps (2x4) of 64x32 warp tiles, cp.async 2-stage.
// smem tile: [128 rows][32 halves], 16B chunk swizzle: chunk ^= (row>>1)&3.
#define GEMM_SMEM 65536
#define TILE_B 8192

__global__ __launch_bounds__(256) void gemm_mma_kernel(
    const __nv_bfloat16* __restrict__ Ahi, const __nv_bfloat16* __restrict__ Alo,
    const __nv_bfloat16* __restrict__ Bhi, const __nv_bfloat16* __restrict__ Blo,
    const float* __restrict__ bias, float* __restrict__ Cmat,
    int M, int N, int K)
{
    extern __shared__ char sm[];
    const uint32_t sbase = smem_u32(sm);

    const int tid  = threadIdx.x;
    const int wid  = tid >> 5;
    const int lane = tid & 31;
    const int m0 = blockIdx.y * 128;
    const int n0 = blockIdx.x * 128;
    const int wm = wid & 1;          // 0..1 -> 64-row slab
    const int wn = wid >> 1;         // 0..3 -> 32-col slab

    // ---- load mapping: 512 x 16B chunks per tile, 2 per thread ----
    const int lr0 = tid >> 2,           lc0 = tid & 3;
    const int lr1 = (tid + 256) >> 2,   lc1 = (tid + 256) & 3;
    const uint32_t so0 = (uint32_t)lr0 * 64 + (uint32_t)((lc0 ^ ((lr0 >> 1) & 3)) * 16);
    const uint32_t so1 = (uint32_t)lr1 * 64 + (uint32_t)((lc1 ^ ((lr1 >> 1) & 3)) * 16);
    const __nv_bfloat16* pAhi0 = Ahi + (size_t)(m0 + lr0) * K + lc0 * 8;
    const __nv_bfloat16* pAhi1 = Ahi + (size_t)(m0 + lr1) * K + lc1 * 8;
    const __nv_bfloat16* pAlo0 = Alo + (size_t)(m0 + lr0) * K + lc0 * 8;
    const __nv_bfloat16* pAlo1 = Alo + (size_t)(m0 + lr1) * K + lc1 * 8;
    const __nv_bfloat16* pBhi0 = Bhi + (size_t)(n0 + lr0) * K + lc0 * 8;
    const __nv_bfloat16* pBhi1 = Bhi + (size_t)(n0 + lr1) * K + lc1 * 8;
    const __nv_bfloat16* pBlo0 = Blo + (size_t)(n0 + lr0) * K + lc0 * 8;
    const __nv_bfloat16* pBlo1 = Blo + (size_t)(n0 + lr1) * K + lc1 * 8;

    float acc[4][4][4];
    #pragma unroll
    for (int i = 0; i < 4; i++)
        #pragma unroll
        for (int j = 0; j < 4; j++)
            #pragma unroll
            for (int c = 0; c < 4; c++) acc[i][j][c] = 0.f;

    const int nch = K >> 5;

    // ---- ldmatrix address precompute (row-dependent part) ----
    // A: rows wm*64 + mi*16 + (lane&15); B: rows wn*32 + bni*16 + (lane&15)
    const int lrow = lane & 15;
    const int kc   = lane >> 4;          // 0..1 -> +8 halves within k16

    // prologue: stage 0
    {
        CP16(sbase + 0 * TILE_B + so0, pAhi0);
        CP16(sbase + 0 * TILE_B + so1, pAhi1);
        CP16(sbase + 1 * TILE_B + so0, pAlo0);
        CP16(sbase + 1 * TILE_B + so1, pAlo1);
        CP16(sbase + 2 * TILE_B + so0, pBhi0);
        CP16(sbase + 2 * TILE_B + so1, pBhi1);
        CP16(sbase + 3 * TILE_B + so0, pBlo0);
        CP16(sbase + 3 * TILE_B + so1, pBlo1);
        CP_COMMIT();
    }

    for (int ch = 0; ch < nch; ch++) {
        if (ch + 1 < nch) {
            const uint32_t sb = sbase + ((ch + 1) & 1) * 32768;
            const int kb = (ch + 1) << 5;
            CP16(sb + 0 * TILE_B + so0, pAhi0 + kb);
            CP16(sb + 0 * TILE_B + so1, pAhi1 + kb);
            CP16(sb + 1 * TILE_B + so0, pAlo0 + kb);
            CP16(sb + 1 * TILE_B + so1, pAlo1 + kb);
            CP16(sb + 2 * TILE_B + so0, pBhi0 + kb);
            CP16(sb + 2 * TILE_B + so1, pBhi1 + kb);
            CP16(sb + 3 * TILE_B + so0, pBlo0 + kb);
            CP16(sb + 3 * TILE_B + so1, pBlo1 + kb);
            CP_COMMIT();
            CP_WAIT1();
        } else {
            CP_WAIT0();
        }
        __syncthreads();

        const uint32_t st = sbase + (ch & 1) * 32768;

        #pragma unroll
        for (int kk = 0; kk < 2; kk++) {
            const int chunk = kk * 2 + kc;
            uint32_t ahi[4][4], alo[4][4];
            #pragma unroll
            for (int mi = 0; mi < 4; mi++) {
                const int r = wm * 64 + mi * 16 + lrow;
                const uint32_t off = (uint32_t)r * 64 +
                    (uint32_t)((chunk ^ ((r >> 1) & 3)) * 16);
                LDSM_X4(ahi[mi][0], ahi[mi][1], ahi[mi][2], ahi[mi][3],
                        st + 0 * TILE_B + off);
                LDSM_X4(alo[mi][0], alo[mi][1], alo[mi][2], alo[mi][3],
                        st + 1 * TILE_B + off);
            }
            uint32_t bhi[2][4], blo[2][4];
            #pragma unroll
            for (int g = 0; g < 2; g++) {
                const int r = wn * 32 + g * 16 + lrow;
                const uint32_t off = (uint32_t)r * 64 +
                    (uint32_t)((chunk ^ ((r >> 1) & 3)) * 16);
                LDSM_X4(bhi[g][0], bhi[g][1], bhi[g][2], bhi[g][3],
                        st + 2 * TILE_B + off);
                LDSM_X4(blo[g][0], blo[g][1], blo[g][2], blo[g][3],
                        st + 3 * TILE_B + off);
            }
            // mats in x4: {rows0-7 k0-7, rows8-15 k0-7, rows0-7 k8-15, rows8-15 k8-15}
            // n-tile (g,o): o=0 -> rows g*16+0..7: regs {b[0], b[2]}; o=1 -> {b[1], b[3]}
            #pragma unroll
            for (int mi = 0; mi < 4; mi++) {
                #pragma unroll
                for (int ni = 0; ni < 4; ni++) {
                    const int g = ni >> 1, o = ni & 1;
                    MMA_BF16(acc[mi][ni], ahi[mi], bhi[g][o], bhi[g][2 + o]);
                    MMA_BF16(acc[mi][ni], ahi[mi], blo[g][o], blo[g][2 + o]);
                    MMA_BF16(acc[mi][ni], alo[mi], bhi[g][o], bhi[g][2 + o]);
                }
            }
        }
        __syncthreads();
    }

    // ---- epilogue: bias add, store ----
    const int orow = lane >> 2;          // 0..7
    const int ocol = (lane & 3) * 2;
    #pragma unroll
    for (int mi = 0; mi < 4; mi++) {
        const int r0 = m0 + wm * 64 + mi * 16 + orow;
        #pragma unroll
        for (int ni = 0; ni < 4; ni++) {
            const int c = n0 + wn * 32 + ni * 8 + ocol;
            const float b0 = bias[c], b1 = bias[c + 1];
            float2 v0 = make_float2(acc[mi][ni][0] + b0, acc[mi][ni][1] + b1);
            float2 v1 = make_float2(acc[mi][ni][2] + b0, acc[mi][ni][3] + b1);
            *(float2*)(Cmat + (size_t)r0 * N + c)       = v0;
            *(float2*)(Cmat + (size_t)(r0 + 8) * N + c) = v1;
        }
    }
}

// ---------------- Lorentz expmap transform ----------------------------------
__global__ void transform_kernel() {
    int wid = blockIdx.x * (blockDim.x / 32) + (threadIdx.x >> 5);
    int lane = threadIdx.x & 31;
    int t = wid % T_;
    int h = (wid / T_) % H_;
    int b = wid / (T_ * H_);
    const float* base = g_qkv + ((size_t)(b * T_ + t)) * (3 * C_);
    size_t outoff = ((size_t)(b * H_ + h) * T_ + t) * D_;

    {
        const float* u = base + 0 * C_ + h * D_;
        float lo = u[lane], hi = u[lane + 32];
        float ss = lo * lo + hi * hi;
        #pragma unroll
        for (int m = 16; m; m >>= 1) ss += __shfl_xor_sync(0xffffffffu, ss, m);
        float u0 = __shfl_sync(0xffffffffu, lo, 0);
        float mink = ss - 2.f * u0 * u0;
        float n = sqrtf(fmaxf(mink, 1e-8f));
        float tme = coshf(n);
        float coef = sinhf(n) / n;
        g_Qp[outoff + lane]      = (lane == 0) ? tme : coef * lo;
        g_Qp[outoff + lane + 32] = coef * hi;
    }
    {
        const float* u = base + 1 * C_ + h * D_;
        float lo = u[lane], hi = u[lane + 32];
        float ss = lo * lo + hi * hi;
        #pragma unroll
        for (int m = 16; m; m >>= 1) ss += __shfl_xor_sync(0xffffffffu, ss, m);
        float u0 = __shfl_sync(0xffffffffu, lo, 0);
        float mink = ss - 2.f * u0 * u0;
        float n = sqrtf(fmaxf(mink, 1e-8f));
        float tme = coshf(n);
        float coef = sinhf(n) / n;
        g_Kp[outoff + lane]      = (lane == 0) ? tme : -coef * lo;
        g_Kp[outoff + lane + 32] = -coef * hi;
    }
    {
        const float* u = base + 2 * C_ + h * D_;
        g_V[outoff + lane]      = u[lane];
        g_V[outoff + lane + 32] = u[lane + 32];
    }
}

// ---------------- flash attention with Lorentz score transform --------------
#define APAD 65
#define ATTN_SMEM (4 * 64 * APAD * 4)

__global__ __launch_bounds__(256) void attn_kernel() {
    extern __shared__ float smf[];
    float* Qs = smf;
    float* Ks = smf + 64 * APAD;
    float* Vs = smf + 2 * 64 * APAD;
    float* Ps = smf + 3 * 64 * APAD;

    int ti = blockIdx.x;
    int h  = blockIdx.y;
    int b  = blockIdx.z;
    int bh = b * H_ + h;
    int tid = threadIdx.x;
    int tr = tid / 16;
    int tc = tid % 16;
    int i0 = ti * 64;

    const float* Qg = g_Qp + ((size_t)bh * T_ + i0) * D_;

    #pragma unroll
    for (int it = 0; it < 4; it++) {
        int id = tid + it * 256;
        int r = id >> 4, c4 = (id & 15) * 4;
        float4 v = *(const float4*)(Qg + (size_t)r * D_ + c4);
        Qs[r * APAD + c4 + 0] = v.x;
        Qs[r * APAD + c4 + 1] = v.y;
        Qs[r * APAD + c4 + 2] = v.z;
        Qs[r * APAD + c4 + 3] = v.w;
    }

    float m_r[4], l_r[4], O[4][4];
    #pragma unroll
    for (int i = 0; i < 4; i++) {
        m_r[i] = -1e30f; l_r[i] = 0.f;
        #pragma unroll
        for (int j = 0; j < 4; j++) O[i][j] = 0.f;
    }
    __syncthreads();

    for (int tj = 0; tj <= ti; tj++) {
        int j0 = tj * 64;
        const float* Kg = g_Kp + ((size_t)bh * T_ + j0) * D_;
        const float* Vg = g_V  + ((size_t)bh * T_ + j0) * D_;
        #pragma unroll
        for (int it = 0; it < 4; it++) {
            int id = tid + it * 256;
            int r = id >> 4, c4 = (id & 15) * 4;
            float4 v = *(const float4*)(Kg + (size_t)r * D_ + c4);
            Ks[r * APAD + c4 + 0] = v.x;
            Ks[r * APAD + c4 + 1] = v.y;
            Ks[r * APAD + c4 + 2] = v.z;
            Ks[r * APAD + c4 + 3] = v.w;
            float4 w = *(const float4*)(Vg + (size_t)r * D_ + c4);
            Vs[r * APAD + c4 + 0] = w.x;
            Vs[r * APAD + c4 + 1] = w.y;
            Vs[r * APAD + c4 + 2] = w.z;
            Vs[r * APAD + c4 + 3] = w.w;
        }
        __syncthreads();

        float acc[4][4];
        #pragma unroll
        for (int i = 0; i < 4; i++)
            #pragma unroll
            for (int j = 0; j < 4; j++) acc[i][j] = 0.f;
        #pragma unroll 8
        for (int d = 0; d < 64; d++) {
            float a[4], bb[4];
            #pragma unroll
            for (int i = 0; i < 4; i++) a[i]  = Qs[(tr * 4 + i) * APAD + d];
            #pragma unroll
            for (int j = 0; j < 4; j++) bb[j] = Ks[(tc * 4 + j) * APAD + d];
            #pragma unroll
            for (int i = 0; i < 4; i++)
                #pragma unroll
                for (int j = 0; j < 4; j++)
                    acc[i][j] += a[i] * bb[j];
        }

        bool diag = (tj == ti);
        #pragma unroll
        for (int i = 0; i < 4; i++) {
            int rg = tr * 4 + i;
            #pragma unroll
            for (int j = 0; j < 4; j++) {
                int cg = tc * 4 + j;
                float xni = fmaxf(acc[i][j], 1.0f + 1e-7f);
                float dd = __logf(xni + sqrtf(xni * xni - 1.0f));
                float sc = -dd * dd * 0.125f;
                if (diag && cg > rg) sc = -1e30f;
                acc[i][j] = sc;
            }
        }

        #pragma unroll
        for (int i = 0; i < 4; i++) {
            float mx = acc[i][0];
            #pragma unroll
            for (int j = 1; j < 4; j++) mx = fmaxf(mx, acc[i][j]);
            #pragma unroll
            for (int m = 8; m; m >>= 1)
                mx = fmaxf(mx, __shfl_xor_sync(0xffffffffu, mx, m));
            float mnew = fmaxf(m_r[i], mx);
            float scale = __expf(m_r[i] - mnew);
            l_r[i] *= scale;
            #pragma unroll
            for (int j = 0; j < 4; j++) O[i][j] *= scale;
            float rs = 0.f;
            #pragma unroll
            for (int j = 0; j < 4; j++) {
                float p = __expf(acc[i][j] - mnew);
                acc[i][j] = p;
                rs += p;
            }
            #pragma unroll
            for (int m = 8; m; m >>= 1)
                rs += __shfl_xor_sync(0xffffffffu, rs, m);
            l_r[i] += rs;
            m_r[i] = mnew;
        }

        #pragma unroll
        for (int i = 0; i < 4; i++)
            #pragma unroll
            for (int j = 0; j < 4; j++)
                Ps[(tr * 4 + i) * APAD + tc * 4 + j] = acc[i][j];
        __syncthreads();

        #pragma unroll 4
        for (int j = 0; j < 64; j++) {
            float p[4], v[4];
            #pragma unroll
            for (int i = 0; i < 4; i++) p[i] = Ps[(tr * 4 + i) * APAD + j];
            #pragma unroll
            for (int jj = 0; jj < 4; jj++) v[jj] = Vs[j * APAD + tc * 4 + jj];
            #pragma unroll
            for (int i = 0; i < 4; i++)
                #pragma unroll
                for (int jj = 0; jj < 4; jj++)
                    O[i][jj] += p[i] * v[jj];
        }
        __syncthreads();
    }

    #pragma unroll
    for (int i = 0; i < 4; i++) {
        int r = i0 + tr * 4 + i;
        float inv = g_spike[b * T_ + r] / l_r[i];
        float* yp = g_Y + ((size_t)(b * T_ + r)) * C_ + h * D_ + tc * 4;
        float4 v;
        v.x = O[i][0] * inv;
        v.y = O[i][1] * inv;
        v.z = O[i][2] * inv;
        v.w = O[i][3] * inv;
        *(float4*)yp = v;
    }
}

// ---------------- launch -----------------------------------------------------
extern "C" void kernel_launch(void* const* d_in, const int* in_sizes, int n_in,
                              void* d_out, int out_size) {
    const float* x      = (const float*)d_in[0];
    const float* W_qkv  = (const float*)d_in[1];
    const float* b_qkv  = (const float*)d_in[2];
    const float* W_out  = (const float*)d_in[3];
    const float* b_out  = (const float*)d_in[4];
    const float* w_sur  = (const float*)d_in[5];
    const float* b_sur  = (const float*)d_in[6];
    const float* thresh = (const float*)d_in[7];
    float* out = (float*)d_out;

    float *p_qkv, *p_Y;
    __nv_bfloat16 *p_xhi, *p_xlo, *p_Wqt_hi, *p_Wqt_lo;
    __nv_bfloat16 *p_Yhi, *p_Ylo, *p_Wot_hi, *p_Wot_lo;
    cudaGetSymbolAddress((void**)&p_qkv, g_qkv);
    cudaGetSymbolAddress((void**)&p_Y,   g_Y);
    cudaGetSymbolAddress((void**)&p_xhi, g_xhi);
    cudaGetSymbolAddress((void**)&p_xlo, g_xlo);
    cudaGetSymbolAddress((void**)&p_Wqt_hi, g_Wqt_hi);
    cudaGetSymbolAddress((void**)&p_Wqt_lo, g_Wqt_lo);
    cudaGetSymbolAddress((void**)&p_Yhi, g_Yhi);
    cudaGetSymbolAddress((void**)&p_Ylo, g_Ylo);
    cudaGetSymbolAddress((void**)&p_Wot_hi, g_Wot_hi);
    cudaGetSymbolAddress((void**)&p_Wot_lo, g_Wot_lo);

    cudaFuncSetAttribute(attn_kernel,
                         cudaFuncAttributeMaxDynamicSharedMemorySize, ATTN_SMEM);
    cudaFuncSetAttribute(gemm_mma_kernel,
                         cudaFuncAttributeMaxDynamicSharedMemorySize, GEMM_SMEM);

    const int M = B_ * T_;   // 4096

    // 1. spike gate
    spike_kernel<<<M / 8, 256>>>(x, w_sur, b_sur, thresh);

    // 2. operand prep for QKV GEMM
    split_kernel<<<(M * C_ / 4 + 255) / 256, 256>>>(x, p_xhi, p_xlo, M * C_ / 4);
    transpose_split_kernel<<<dim3(3 * C_ / 32, C_ / 32), dim3(32, 8)>>>(
        W_qkv, p_Wqt_hi, p_Wqt_lo, C_, 3 * C_);

    // 3. QKV GEMM (mma.sync bf16x3): (4096 x 1024) @ (1024 x 3072) + b
    gemm_mma_kernel<<<dim3(3 * C_ / 128, M / 128), 256, GEMM_SMEM>>>(
        p_xhi, p_xlo, p_Wqt_hi, p_Wqt_lo, b_qkv, p_qkv, M, 3 * C_, C_);

    // 4. Lorentz transform
    transform_kernel<<<(B_ * H_ * T_) / 8, 256>>>();

    // 5. flash attention
    attn_kernel<<<dim3(T_ / 64, H_, B_), 256, ATTN_SMEM>>>();

    // 6. operand prep + out projection
    split_kernel<<<(M * C_ / 4 + 255) / 256, 256>>>(p_Y, p_Yhi, p_Ylo, M * C_ / 4);
    transpose_split_kernel<<<dim3(C_ / 32, C_ / 32), dim3(32, 8)>>>(
        W_out, p_Wot_hi, p_Wot_lo, C_, C_);
    gemm_mma_kernel<<<dim3(C_ / 128, M / 128), 256, GEMM_SMEM>>>(
        p_Yhi, p_Ylo, p_Wot_hi, p_Wot_lo, b_out, out, M, C_, C_);
}

// round 5
// speedup vs baseline: 1.6251x; 1.0199x over previous
#include <cuda_runtime.h>
#include <cuda_bf16.h>
#include <math.h>
#include <stdint.h>

#define B_ 4
#define T_ 1024
#define C_ 1024
#define H_ 16
#define D_ 64

// ---------------- scratch (device globals; no allocations allowed) ----------
__device__ float g_qkv[(size_t)B_ * T_ * 3 * C_];          // 48 MB
__device__ float g_Qp[(size_t)B_ * H_ * T_ * D_];          // 16 MB
__device__ float g_Kp[(size_t)B_ * H_ * T_ * D_];          // 16 MB
__device__ float g_V [(size_t)B_ * H_ * T_ * D_];          // 16 MB
__device__ float g_Y [(size_t)B_ * T_ * C_];               // 16 MB
__device__ float g_spike[B_ * T_];

// bf16 hi/lo split operands for tensor-core GEMMs
__device__ __nv_bfloat16 g_xhi[(size_t)B_ * T_ * C_];
__device__ __nv_bfloat16 g_xlo[(size_t)B_ * T_ * C_];
__device__ __nv_bfloat16 g_Wqt_hi[(size_t)3 * C_ * C_];    // W_qkv^T [N,K]
__device__ __nv_bfloat16 g_Wqt_lo[(size_t)3 * C_ * C_];
__device__ __nv_bfloat16 g_Yhi[(size_t)B_ * T_ * C_];
__device__ __nv_bfloat16 g_Ylo[(size_t)B_ * T_ * C_];
__device__ __nv_bfloat16 g_Wot_hi[(size_t)C_ * C_];        // W_out^T [N,K]
__device__ __nv_bfloat16 g_Wot_lo[(size_t)C_ * C_];

// ======================= generic-PTX helpers (no 'a' features) ==============
__device__ __forceinline__ uint32_t smem_u32(const void* p) {
    uint32_t a;
    asm("{ .reg .u64 t; cvta.to.shared.u64 t, %1; cvt.u32.u64 %0, t; }"
        : "=r"(a) : "l"(p));
    return a;
}
#define CP16(saddr, gaddr) \
    asm volatile("cp.async.cg.shared.global [%0], [%1], 16;" \
                 :: "r"(saddr), "l"(gaddr))
#define CP_COMMIT() asm volatile("cp.async.commit_group;" ::: "memory")
#define CP_WAIT1()  asm volatile("cp.async.wait_group 1;" ::: "memory")

#define LDSM_X4(r0, r1, r2, r3, addr) \
    asm volatile("ldmatrix.sync.aligned.m8n8.x4.shared.b16 {%0,%1,%2,%3}, [%4];" \
                 : "=r"(r0), "=r"(r1), "=r"(r2), "=r"(r3) : "r"(addr))

#define MMA_BF16(d, a, b0, b1) \
    asm volatile("mma.sync.aligned.m16n8k16.row.col.f32.bf16.bf16.f32 " \
                 "{%0,%1,%2,%3}, {%4,%5,%6,%7}, {%8,%9}, {%0,%1,%2,%3};" \
                 : "+f"((d)[0]), "+f"((d)[1]), "+f"((d)[2]), "+f"((d)[3]) \
                 : "r"((a)[0]), "r"((a)[1]), "r"((a)[2]), "r"((a)[3]), \
                   "r"(b0), "r"(b1))

// ---------------- spike gate -------------------------------------------------
__global__ void spike_kernel(const float* __restrict__ x,
                             const float* __restrict__ w_sur,
                             const float* __restrict__ b_sur,
                             const float* __restrict__ threshold) {
    int row = blockIdx.x * (blockDim.x / 32) + (threadIdx.x >> 5);
    int lane = threadIdx.x & 31;
    const float* xr = x + (size_t)row * C_;
    float s = 0.f;
    #pragma unroll 4
    for (int i = lane; i < C_; i += 32) s += xr[i] * w_sur[i];
    #pragma unroll
    for (int m = 16; m; m >>= 1) s += __shfl_xor_sync(0xffffffffu, s, m);
    if (lane == 0) {
        float z = s + b_sur[0];
        float imp = 1.f / (1.f + expf(-z));
        g_spike[row] = (imp > threshold[0]) ? 1.f : 0.f;
    }
}

// ---------------- fp32 -> bf16 hi/lo split (elementwise) --------------------
__global__ void split_kernel(const float* __restrict__ src,
                             __nv_bfloat16* __restrict__ hi,
                             __nv_bfloat16* __restrict__ lo, int n4) {
    int i = blockIdx.x * blockDim.x + threadIdx.x;
    if (i >= n4) return;
    float4 v = *(const float4*)(src + (size_t)i * 4);
    __nv_bfloat16 h0 = __float2bfloat16(v.x);
    __nv_bfloat16 h1 = __float2bfloat16(v.y);
    __nv_bfloat16 h2 = __float2bfloat16(v.z);
    __nv_bfloat16 h3 = __float2bfloat16(v.w);
    __nv_bfloat16 l0 = __float2bfloat16(v.x - __bfloat162float(h0));
    __nv_bfloat16 l1 = __float2bfloat16(v.y - __bfloat162float(h1));
    __nv_bfloat16 l2 = __float2bfloat16(v.z - __bfloat162float(h2));
    __nv_bfloat16 l3 = __float2bfloat16(v.w - __bfloat162float(h3));
    __nv_bfloat162* hp = (__nv_bfloat162*)(hi + (size_t)i * 4);
    __nv_bfloat162* lp = (__nv_bfloat162*)(lo + (size_t)i * 4);
    hp[0] = __nv_bfloat162(h0, h1); hp[1] = __nv_bfloat162(h2, h3);
    lp[0] = __nv_bfloat162(l0, l1); lp[1] = __nv_bfloat162(l2, l3);
}

// ---------------- W[K,N] -> W^T[N,K] bf16 hi/lo split -----------------------
__global__ void transpose_split_kernel(const float* __restrict__ W,
                                       __nv_bfloat16* __restrict__ Thi,
                                       __nv_bfloat16* __restrict__ Tlo,
                                       int K, int N) {
    __shared__ float tile[32][33];
    int k0 = blockIdx.y * 32, n0 = blockIdx.x * 32;
    int tx = threadIdx.x, ty = threadIdx.y;    // 32 x 8
    #pragma unroll
    for (int j = 0; j < 32; j += 8)
        tile[ty + j][tx] = W[(size_t)(k0 + ty + j) * N + n0 + tx];
    __syncthreads();
    #pragma unroll
    for (int j = 0; j < 32; j += 8) {
        float v = tile[tx][ty + j];
        __nv_bfloat16 h = __float2bfloat16(v);
        __nv_bfloat16 l = __float2bfloat16(v - __bfloat162float(h));
        Thi[(size_t)(n0 + ty + j) * K + k0 + tx] = h;
        Tlo[(size_t)(n0 + ty + j) * K + k0 + tx] = l;
    }
}

// ---------------- mma.sync bf16x3 GEMM: C = A @ B^T + bias ------------------
// A[M,K] hi/lo bf16 (K-major), B[N,K] hi/lo bf16 (K-major).
// CTA 128x128, BK=32, 8 warps (2x4) of 64x32 warp tiles, cp.async 3-stage.
// smem tile: [128 rows][32 halves], 16B chunk swizzle: chunk ^= (row>>1)&3.
#define STAGE_B 32768
#define GEMM_SMEM (3 * STAGE_B)
#define TILE_B 8192

__global__ __launch_bounds__(256) void gemm_mma_kernel(
    const __nv_bfloat16* __restrict__ Ahi, const __nv_bfloat16* __restrict__ Alo,
    const __nv_bfloat16* __restrict__ Bhi, const __nv_bfloat16* __restrict__ Blo,
    const float* __restrict__ bias, float* __restrict__ Cmat,
    int M, int N, int K)
{
    extern __shared__ char sm[];
    const uint32_t sbase = smem_u32(sm);

    const int tid  = threadIdx.x;
    const int wid  = tid >> 5;
    const int lane = tid & 31;
    const int m0 = blockIdx.y * 128;
    const int n0 = blockIdx.x * 128;
    const int wm = wid & 1;          // 0..1 -> 64-row slab
    const int wn = wid >> 1;         // 0..3 -> 32-col slab

    // ---- load mapping: 512 x 16B chunks per tile, 2 per thread ----
    const int lr0 = tid >> 2,           lc0 = tid & 3;
    const int lr1 = (tid + 256) >> 2,   lc1 = (tid + 256) & 3;
    const uint32_t so0 = (uint32_t)lr0 * 64 + (uint32_t)((lc0 ^ ((lr0 >> 1) & 3)) * 16);
    const uint32_t so1 = (uint32_t)lr1 * 64 + (uint32_t)((lc1 ^ ((lr1 >> 1) & 3)) * 16);
    const __nv_bfloat16* pAhi0 = Ahi + (size_t)(m0 + lr0) * K + lc0 * 8;
    const __nv_bfloat16* pAhi1 = Ahi + (size_t)(m0 + lr1) * K + lc1 * 8;
    const __nv_bfloat16* pAlo0 = Alo + (size_t)(m0 + lr0) * K + lc0 * 8;
    const __nv_bfloat16* pAlo1 = Alo + (size_t)(m0 + lr1) * K + lc1 * 8;
    const __nv_bfloat16* pBhi0 = Bhi + (size_t)(n0 + lr0) * K + lc0 * 8;
    const __nv_bfloat16* pBhi1 = Bhi + (size_t)(n0 + lr1) * K + lc1 * 8;
    const __nv_bfloat16* pBlo0 = Blo + (size_t)(n0 + lr0) * K + lc0 * 8;
    const __nv_bfloat16* pBlo1 = Blo + (size_t)(n0 + lr1) * K + lc1 * 8;

    float acc[4][4][4];
    #pragma unroll
    for (int i = 0; i < 4; i++)
        #pragma unroll
        for (int j = 0; j < 4; j++)
            #pragma unroll
            for (int c = 0; c < 4; c++) acc[i][j][c] = 0.f;

    const int nch = K >> 5;
    const int lrow = lane & 15;
    const int kc   = lane >> 4;          // 0..1 -> +8 halves within k16

    // prologue: stages 0 and 1
    #pragma unroll
    for (int s = 0; s < 2; s++) {
        const uint32_t sb = sbase + (uint32_t)s * STAGE_B;
        const int kb = s << 5;
        CP16(sb + 0 * TILE_B + so0, pAhi0 + kb);
        CP16(sb + 0 * TILE_B + so1, pAhi1 + kb);
        CP16(sb + 1 * TILE_B + so0, pAlo0 + kb);
        CP16(sb + 1 * TILE_B + so1, pAlo1 + kb);
        CP16(sb + 2 * TILE_B + so0, pBhi0 + kb);
        CP16(sb + 2 * TILE_B + so1, pBhi1 + kb);
        CP16(sb + 3 * TILE_B + so0, pBlo0 + kb);
        CP16(sb + 3 * TILE_B + so1, pBlo1 + kb);
        CP_COMMIT();
    }

    for (int ch = 0; ch < nch; ch++) {
        CP_WAIT1();                    // group ch complete (commit-always FIFO)
        __syncthreads();               // everyone done with stage (ch%3) reuse hazard

        if (ch + 2 < nch) {            // prefetch stage ch+2 (distance 2)
            const uint32_t sb = sbase + (uint32_t)((ch + 2) % 3) * STAGE_B;
            const int kb = (ch + 2) << 5;
            CP16(sb + 0 * TILE_B + so0, pAhi0 + kb);
            CP16(sb + 0 * TILE_B + so1, pAhi1 + kb);
            CP16(sb + 1 * TILE_B + so0, pAlo0 + kb);
            CP16(sb + 1 * TILE_B + so1, pAlo1 + kb);
            CP16(sb + 2 * TILE_B + so0, pBhi0 + kb);
            CP16(sb + 2 * TILE_B + so1, pBhi1 + kb);
            CP16(sb + 3 * TILE_B + so0, pBlo0 + kb);
            CP16(sb + 3 * TILE_B + so1, pBlo1 + kb);
        }
        CP_COMMIT();                   // always (empty groups keep FIFO math)

        const uint32_t st = sbase + (uint32_t)(ch % 3) * STAGE_B;

        #pragma unroll
        for (int kk = 0; kk < 2; kk++) {
            const int chunk = kk * 2 + kc;
            uint32_t ahi[4][4], alo[4][4];
            #pragma unroll
            for (int mi = 0; mi < 4; mi++) {
                const int r = wm * 64 + mi * 16 + lrow;
                const uint32_t off = (uint32_t)r * 64 +
                    (uint32_t)((chunk ^ ((r >> 1) & 3)) * 16);
                LDSM_X4(ahi[mi][0], ahi[mi][1], ahi[mi][2], ahi[mi][3],
                        st + 0 * TILE_B + off);
                LDSM_X4(alo[mi][0], alo[mi][1], alo[mi][2], alo[mi][3],
                        st + 1 * TILE_B + off);
            }
            uint32_t bhi[2][4], blo[2][4];
            #pragma unroll
            for (int g = 0; g < 2; g++) {
                const int r = wn * 32 + g * 16 + lrow;
                const uint32_t off = (uint32_t)r * 64 +
                    (uint32_t)((chunk ^ ((r >> 1) & 3)) * 16);
                LDSM_X4(bhi[g][0], bhi[g][1], bhi[g][2], bhi[g][3],
                        st + 2 * TILE_B + off);
                LDSM_X4(blo[g][0], blo[g][1], blo[g][2], blo[g][3],
                        st + 3 * TILE_B + off);
            }
            #pragma unroll
            for (int mi = 0; mi < 4; mi++) {
                #pragma unroll
                for (int ni = 0; ni < 4; ni++) {
                    const int g = ni >> 1, o = ni & 1;
                    MMA_BF16(acc[mi][ni], ahi[mi], bhi[g][o], bhi[g][2 + o]);
                    MMA_BF16(acc[mi][ni], ahi[mi], blo[g][o], blo[g][2 + o]);
                    MMA_BF16(acc[mi][ni], alo[mi], bhi[g][o], bhi[g][2 + o]);
                }
            }
        }
        // no trailing sync: stage reuse protected by top-of-iter barrier
    }

    // ---- epilogue: bias add, store ----
    const int orow = lane >> 2;          // 0..7
    const int ocol = (lane & 3) * 2;
    #pragma unroll
    for (int mi = 0; mi < 4; mi++) {
        const int r0 = m0 + wm * 64 + mi * 16 + orow;
        #pragma unroll
        for (int ni = 0; ni < 4; ni++) {
            const int c = n0 + wn * 32 + ni * 8 + ocol;
            const float b0 = bias[c], b1 = bias[c + 1];
            float2 v0 = make_float2(acc[mi][ni][0] + b0, acc[mi][ni][1] + b1);
            float2 v1 = make_float2(acc[mi][ni][2] + b0, acc[mi][ni][3] + b1);
            *(float2*)(Cmat + (size_t)r0 * N + c)       = v0;
            *(float2*)(Cmat + (size_t)(r0 + 8) * N + c) = v1;
        }
    }
}

// ---------------- Lorentz expmap transform ----------------------------------
__global__ void transform_kernel() {
    int wid = blockIdx.x * (blockDim.x / 32) + (threadIdx.x >> 5);
    int lane = threadIdx.x & 31;
    int t = wid % T_;
    int h = (wid / T_) % H_;
    int b = wid / (T_ * H_);
    const float* base = g_qkv + ((size_t)(b * T_ + t)) * (3 * C_);
    size_t outoff = ((size_t)(b * H_ + h) * T_ + t) * D_;

    {
        const float* u = base + 0 * C_ + h * D_;
        float lo = u[lane], hi = u[lane + 32];
        float ss = lo * lo + hi * hi;
        #pragma unroll
        for (int m = 16; m; m >>= 1) ss += __shfl_xor_sync(0xffffffffu, ss, m);
        float u0 = __shfl_sync(0xffffffffu, lo, 0);
        float mink = ss - 2.f * u0 * u0;
        float n = sqrtf(fmaxf(mink, 1e-8f));
        float tme = coshf(n);
        float coef = sinhf(n) / n;
        g_Qp[outoff + lane]      = (lane == 0) ? tme : coef * lo;
        g_Qp[outoff + lane + 32] = coef * hi;
    }
    {
        const float* u = base + 1 * C_ + h * D_;
        float lo = u[lane], hi = u[lane + 32];
        float ss = lo * lo + hi * hi;
        #pragma unroll
        for (int m = 16; m; m >>= 1) ss += __shfl_xor_sync(0xffffffffu, ss, m);
        float u0 = __shfl_sync(0xffffffffu, lo, 0);
        float mink = ss - 2.f * u0 * u0;
        float n = sqrtf(fmaxf(mink, 1e-8f));
        float tme = coshf(n);
        float coef = sinhf(n) / n;
        g_Kp[outoff + lane]      = (lane == 0) ? tme : -coef * lo;
        g_Kp[outoff + lane + 32] = -coef * hi;
    }
    {
        const float* u = base + 2 * C_ + h * D_;
        g_V[outoff + lane]      = u[lane];
        g_V[outoff + lane + 32] = u[lane + 32];
    }
}

// ---------------- flash attention with Lorentz score transform --------------
// smem: Qt[d][row] and Kt[d][col] transposed (pad 68) for LDS.128 inner loops;
// Vs[row][d] natural; Ps[row][col] for the PV stage.
#define QP 68
#define ATTN_SMEM (4 * 64 * QP * 4)

__global__ __launch_bounds__(256) void attn_kernel() {
    extern __shared__ float smf[];
    float* Qt = smf;                    // [64 d][64 row]
    float* Kt = smf + 64 * QP;          // [64 d][64 col]
    float* Vs = smf + 2 * 64 * QP;      // [64 row][64 d]
    float* Ps = smf + 3 * 64 * QP;      // [64 row][64 col]

    int ti = blockIdx.x;
    int h  = blockIdx.y;
    int b  = blockIdx.z;
    int bh = b * H_ + h;
    int tid = threadIdx.x;
    int tr = tid / 16;
    int tc = tid % 16;
    int i0 = ti * 64;

    const float* Qg = g_Qp + ((size_t)bh * T_ + i0) * D_;

    // fill Qt transposed: r-major lanes -> conflict-free STS
    #pragma unroll
    for (int it = 0; it < 4; it++) {
        int id = tid + it * 256;
        int r = id & 63, cb = id >> 6;            // row, 4-col block
        float4 v = *(const float4*)(Qg + (size_t)r * D_ + cb * 4);
        Qt[(cb * 4 + 0) * QP + r] = v.x;
        Qt[(cb * 4 + 1) * QP + r] = v.y;
        Qt[(cb * 4 + 2) * QP + r] = v.z;
        Qt[(cb * 4 + 3) * QP + r] = v.w;
    }

    float m_r[4], l_r[4], O[4][4];
    #pragma unroll
    for (int i = 0; i < 4; i++) {
        m_r[i] = -1e30f; l_r[i] = 0.f;
        #pragma unroll
        for (int j = 0; j < 4; j++) O[i][j] = 0.f;
    }
    __syncthreads();

    for (int tj = 0; tj <= ti; tj++) {
        int j0 = tj * 64;
        const float* Kg = g_Kp + ((size_t)bh * T_ + j0) * D_;
        const float* Vg = g_V  + ((size_t)bh * T_ + j0) * D_;
        #pragma unroll
        for (int it = 0; it < 4; it++) {
            int id = tid + it * 256;
            int r = id & 63, cb = id >> 6;
            float4 v = *(const float4*)(Kg + (size_t)r * D_ + cb * 4);
            Kt[(cb * 4 + 0) * QP + r] = v.x;
            Kt[(cb * 4 + 1) * QP + r] = v.y;
            Kt[(cb * 4 + 2) * QP + r] = v.z;
            Kt[(cb * 4 + 3) * QP + r] = v.w;
            int r2 = id >> 4, c4 = (id & 15) * 4;
            float4 w = *(const float4*)(Vg + (size_t)r2 * D_ + c4);
            *(float4*)&Vs[r2 * QP + c4] = w;
        }
        __syncthreads();

        // S = Q' K'^T : 2x LDS.128 + 16 FMA per d
        float acc[4][4];
        #pragma unroll
        for (int i = 0; i < 4; i++)
            #pragma unroll
            for (int j = 0; j < 4; j++) acc[i][j] = 0.f;
        #pragma unroll 16
        for (int d = 0; d < 64; d++) {
            float4 a4 = *(const float4*)&Qt[d * QP + tr * 4];
            float4 b4 = *(const float4*)&Kt[d * QP + tc * 4];
            acc[0][0] += a4.x * b4.x; acc[0][1] += a4.x * b4.y;
            acc[0][2] += a4.x * b4.z; acc[0][3] += a4.x * b4.w;
            acc[1][0] += a4.y * b4.x; acc[1][1] += a4.y * b4.y;
            acc[1][2] += a4.y * b4.z; acc[1][3] += a4.y * b4.w;
            acc[2][0] += a4.z * b4.x; acc[2][1] += a4.z * b4.y;
            acc[2][2] += a4.z * b4.z; acc[2][3] += a4.z * b4.w;
            acc[3][0] += a4.w * b4.x; acc[3][1] += a4.w * b4.y;
            acc[3][2] += a4.w * b4.z; acc[3][3] += a4.w * b4.w;
        }

        // Lorentz transform + causal mask on diagonal tile
        bool diag = (tj == ti);
        #pragma unroll
        for (int i = 0; i < 4; i++) {
            int rg = tr * 4 + i;
            #pragma unroll
            for (int j = 0; j < 4; j++) {
                int cg = tc * 4 + j;
                float xni = fmaxf(acc[i][j], 1.0f + 1e-7f);
                float dd = __logf(xni + sqrtf(xni * xni - 1.0f));
                float sc = -dd * dd * 0.125f;
                if (diag && cg > rg) sc = -1e30f;
                acc[i][j] = sc;
            }
        }

        // online softmax
        #pragma unroll
        for (int i = 0; i < 4; i++) {
            float mx = acc[i][0];
            #pragma unroll
            for (int j = 1; j < 4; j++) mx = fmaxf(mx, acc[i][j]);
            #pragma unroll
            for (int m = 8; m; m >>= 1)
                mx = fmaxf(mx, __shfl_xor_sync(0xffffffffu, mx, m));
            float mnew = fmaxf(m_r[i], mx);
            float scale = __expf(m_r[i] - mnew);
            l_r[i] *= scale;
            #pragma unroll
            for (int j = 0; j < 4; j++) O[i][j] *= scale;
            float rs = 0.f;
            #pragma unroll
            for (int j = 0; j < 4; j++) {
                float p = __expf(acc[i][j] - mnew);
                acc[i][j] = p;
                rs += p;
            }
            #pragma unroll
            for (int m = 8; m; m >>= 1)
                rs += __shfl_xor_sync(0xffffffffu, rs, m);
            l_r[i] += rs;
            m_r[i] = mnew;
        }

        // write P (vectorized), then PV
        #pragma unroll
        for (int i = 0; i < 4; i++)
            *(float4*)&Ps[(tr * 4 + i) * QP + tc * 4] =
                make_float4(acc[i][0], acc[i][1], acc[i][2], acc[i][3]);
        __syncthreads();

        #pragma unroll 4
        for (int j4 = 0; j4 < 64; j4 += 4) {
            float4 p0 = *(const float4*)&Ps[(tr * 4 + 0) * QP + j4];
            float4 p1 = *(const float4*)&Ps[(tr * 4 + 1) * QP + j4];
            float4 p2 = *(const float4*)&Ps[(tr * 4 + 2) * QP + j4];
            float4 p3 = *(const float4*)&Ps[(tr * 4 + 3) * QP + j4];
            float4 v0 = *(const float4*)&Vs[(j4 + 0) * QP + tc * 4];
            float4 v1 = *(const float4*)&Vs[(j4 + 1) * QP + tc * 4];
            float4 v2 = *(const float4*)&Vs[(j4 + 2) * QP + tc * 4];
            float4 v3 = *(const float4*)&Vs[(j4 + 3) * QP + tc * 4];
            O[0][0] += p0.x*v0.x + p0.y*v1.x + p0.z*v2.x + p0.w*v3.x;
            O[0][1] += p0.x*v0.y + p0.y*v1.y + p0.z*v2.y + p0.w*v3.y;
            O[0][2] += p0.x*v0.z + p0.y*v1.z + p0.z*v2.z + p0.w*v3.z;
            O[0][3] += p0.x*v0.w + p0.y*v1.w + p0.z*v2.w + p0.w*v3.w;
            O[1][0] += p1.x*v0.x + p1.y*v1.x + p1.z*v2.x + p1.w*v3.x;
            O[1][1] += p1.x*v0.y + p1.y*v1.y + p1.z*v2.y + p1.w*v3.y;
            O[1][2] += p1.x*v0.z + p1.y*v1.z + p1.z*v2.z + p1.w*v3.z;
            O[1][3] += p1.x*v0.w + p1.y*v1.w + p1.z*v2.w + p1.w*v3.w;
            O[2][0] += p2.x*v0.x + p2.y*v1.x + p2.z*v2.x + p2.w*v3.x;
            O[2][1] += p2.x*v0.y + p2.y*v1.y + p2.z*v2.y + p2.w*v3.y;
            O[2][2] += p2.x*v0.z + p2.y*v1.z + p2.z*v2.z + p2.w*v3.z;
            O[2][3] += p2.x*v0.w + p2.y*v1.w + p2.z*v2.w + p2.w*v3.w;
            O[3][0] += p3.x*v0.x + p3.y*v1.x + p3.z*v2.x + p3.w*v3.x;
            O[3][1] += p3.x*v0.y + p3.y*v1.y + p3.z*v2.y + p3.w*v3.y;
            O[3][2] += p3.x*v0.z + p3.y*v1.z + p3.z*v2.z + p3.w*v3.z;
            O[3][3] += p3.x*v0.w + p3.y*v1.w + p3.z*v2.w + p3.w*v3.w;
        }
        __syncthreads();
    }

    // epilogue: /l, *spike, write Y (B,T,H*D)
    #pragma unroll
    for (int i = 0; i < 4; i++) {
        int r = i0 + tr * 4 + i;
        float inv = g_spike[b * T_ + r] / l_r[i];
        float* yp = g_Y + ((size_t)(b * T_ + r)) * C_ + h * D_ + tc * 4;
        float4 v;
        v.x = O[i][0] * inv;
        v.y = O[i][1] * inv;
        v.z = O[i][2] * inv;
        v.w = O[i][3] * inv;
        *(float4*)yp = v;
    }
}

// ---------------- launch -----------------------------------------------------
extern "C" void kernel_launch(void* const* d_in, const int* in_sizes, int n_in,
                              void* d_out, int out_size) {
    const float* x      = (const float*)d_in[0];
    const float* W_qkv  = (const float*)d_in[1];
    const float* b_qkv  = (const float*)d_in[2];
    const float* W_out  = (const float*)d_in[3];
    const float* b_out  = (const float*)d_in[4];
    const float* w_sur  = (const float*)d_in[5];
    const float* b_sur  = (const float*)d_in[6];
    const float* thresh = (const float*)d_in[7];
    float* out = (float*)d_out;

    float *p_qkv, *p_Y;
    __nv_bfloat16 *p_xhi, *p_xlo, *p_Wqt_hi, *p_Wqt_lo;
    __nv_bfloat16 *p_Yhi, *p_Ylo, *p_Wot_hi, *p_Wot_lo;
    cudaGetSymbolAddress((void**)&p_qkv, g_qkv);
    cudaGetSymbolAddress((void**)&p_Y,   g_Y);
    cudaGetSymbolAddress((void**)&p_xhi, g_xhi);
    cudaGetSymbolAddress((void**)&p_xlo, g_xlo);
    cudaGetSymbolAddress((void**)&p_Wqt_hi, g_Wqt_hi);
    cudaGetSymbolAddress((void**)&p_Wqt_lo, g_Wqt_lo);
    cudaGetSymbolAddress((void**)&p_Yhi, g_Yhi);
    cudaGetSymbolAddress((void**)&p_Ylo, g_Ylo);
    cudaGetSymbolAddress((void**)&p_Wot_hi, g_Wot_hi);
    cudaGetSymbolAddress((void**)&p_Wot_lo, g_Wot_lo);

    cudaFuncSetAttribute(attn_kernel,
                         cudaFuncAttributeMaxDynamicSharedMemorySize, ATTN_SMEM);
    cudaFuncSetAttribute(gemm_mma_kernel,
                         cudaFuncAttributeMaxDynamicSharedMemorySize, GEMM_SMEM);

    const int M = B_ * T_;   // 4096

    // 1. spike gate
    spike_kernel<<<M / 8, 256>>>(x, w_sur, b_sur, thresh);

    // 2. operand prep for QKV GEMM
    split_kernel<<<(M * C_ / 4 + 255) / 256, 256>>>(x, p_xhi, p_xlo, M * C_ / 4);
    transpose_split_kernel<<<dim3(3 * C_ / 32, C_ / 32), dim3(32, 8)>>>(
        W_qkv, p_Wqt_hi, p_Wqt_lo, C_, 3 * C_);

    // 3. QKV GEMM (mma.sync bf16x3): (4096 x 1024) @ (1024 x 3072) + b
    gemm_mma_kernel<<<dim3(3 * C_ / 128, M / 128), 256, GEMM_SMEM>>>(
        p_xhi, p_xlo, p_Wqt_hi, p_Wqt_lo, b_qkv, p_qkv, M, 3 * C_, C_);

    // 4. Lorentz transform
    transform_kernel<<<(B_ * H_ * T_) / 8, 256>>>();

    // 5. flash attention
    attn_kernel<<<dim3(T_ / 64, H_, B_), 256, ATTN_SMEM>>>();

    // 6. operand prep + out projection
    split_kernel<<<(M * C_ / 4 + 255) / 256, 256>>>(p_Y, p_Yhi, p_Ylo, M * C_ / 4);
    transpose_split_kernel<<<dim3(C_ / 32, C_ / 32), dim3(32, 8)>>>(
        W_out, p_Wot_hi, p_Wot_lo, C_, C_);
    gemm_mma_kernel<<<dim3(C_ / 128, M / 128), 256, GEMM_SMEM>>>(
        p_Yhi, p_Ylo, p_Wot_hi, p_Wot_lo, b_out, out, M, C_, C_);
}

// round 6
// speedup vs baseline: 2.3379x; 1.4387x over previous
#include <cuda_runtime.h>
#include <cuda_bf16.h>
#include <math.h>
#include <stdint.h>

#define B_ 4
#define T_ 1024
#define C_ 1024
#define H_ 16
#define D_ 64

// ---------------- scratch (device globals; no allocations allowed) ----------
__device__ float g_qkv[(size_t)B_ * T_ * 3 * C_];          // 48 MB
__device__ float g_Y [(size_t)B_ * T_ * C_];               // 16 MB
__device__ float g_spike[B_ * T_];

// transformed Q',K',V as bf16 hi/lo  [BH][T][64]
__device__ __nv_bfloat16 g_Qhi[(size_t)B_ * H_ * T_ * D_];
__device__ __nv_bfloat16 g_Qlo[(size_t)B_ * H_ * T_ * D_];
__device__ __nv_bfloat16 g_Khi[(size_t)B_ * H_ * T_ * D_];
__device__ __nv_bfloat16 g_Klo[(size_t)B_ * H_ * T_ * D_];
__device__ __nv_bfloat16 g_Vhi[(size_t)B_ * H_ * T_ * D_];
__device__ __nv_bfloat16 g_Vlo[(size_t)B_ * H_ * T_ * D_];

// bf16 hi/lo split operands for tensor-core GEMMs
__device__ __nv_bfloat16 g_xhi[(size_t)B_ * T_ * C_];
__device__ __nv_bfloat16 g_xlo[(size_t)B_ * T_ * C_];
__device__ __nv_bfloat16 g_Wqt_hi[(size_t)3 * C_ * C_];    // W_qkv^T [N,K]
__device__ __nv_bfloat16 g_Wqt_lo[(size_t)3 * C_ * C_];
__device__ __nv_bfloat16 g_Yhi[(size_t)B_ * T_ * C_];
__device__ __nv_bfloat16 g_Ylo[(size_t)B_ * T_ * C_];
__device__ __nv_bfloat16 g_Wot_hi[(size_t)C_ * C_];        // W_out^T [N,K]
__device__ __nv_bfloat16 g_Wot_lo[(size_t)C_ * C_];

// ======================= generic-PTX helpers (no 'a' features) ==============
__device__ __forceinline__ uint32_t smem_u32(const void* p) {
    uint32_t a;
    asm("{ .reg .u64 t; cvta.to.shared.u64 t, %1; cvt.u32.u64 %0, t; }"
        : "=r"(a) : "l"(p));
    return a;
}
#define CP16(saddr, gaddr) \
    asm volatile("cp.async.cg.shared.global [%0], [%1], 16;" \
                 :: "r"(saddr), "l"(gaddr))
#define CP_COMMIT() asm volatile("cp.async.commit_group;" ::: "memory")
#define CP_WAIT1()  asm volatile("cp.async.wait_group 1;" ::: "memory")

#define LDSM_X4(r0, r1, r2, r3, addr) \
    asm volatile("ldmatrix.sync.aligned.m8n8.x4.shared.b16 {%0,%1,%2,%3}, [%4];" \
                 : "=r"(r0), "=r"(r1), "=r"(r2), "=r"(r3) : "r"(addr))

#define LDSM_X4_T(r0, r1, r2, r3, addr) \
    asm volatile("ldmatrix.sync.aligned.m8n8.x4.trans.shared.b16 {%0,%1,%2,%3}, [%4];" \
                 : "=r"(r0), "=r"(r1), "=r"(r2), "=r"(r3) : "r"(addr))

#define MMA_BF16(d, a, b0, b1) \
    asm volatile("mma.sync.aligned.m16n8k16.row.col.f32.bf16.bf16.f32 " \
                 "{%0,%1,%2,%3}, {%4,%5,%6,%7}, {%8,%9}, {%0,%1,%2,%3};" \
                 : "+f"((d)[0]), "+f"((d)[1]), "+f"((d)[2]), "+f"((d)[3]) \
                 : "r"((a)[0]), "r"((a)[1]), "r"((a)[2]), "r"((a)[3]), \
                   "r"(b0), "r"(b1))

__device__ __forceinline__ uint32_t pack_bf16(float a, float b) {
    __nv_bfloat162 h = __floats2bfloat162_rn(a, b);
    return *(uint32_t*)&h;
}

// ---------------- spike gate -------------------------------------------------
__global__ void spike_kernel(const float* __restrict__ x,
                             const float* __restrict__ w_sur,
                             const float* __restrict__ b_sur,
                             const float* __restrict__ threshold) {
    int row = blockIdx.x * (blockDim.x / 32) + (threadIdx.x >> 5);
    int lane = threadIdx.x & 31;
    const float* xr = x + (size_t)row * C_;
    float s = 0.f;
    #pragma unroll 4
    for (int i = lane; i < C_; i += 32) s += xr[i] * w_sur[i];
    #pragma unroll
    for (int m = 16; m; m >>= 1) s += __shfl_xor_sync(0xffffffffu, s, m);
    if (lane == 0) {
        float z = s + b_sur[0];
        float imp = 1.f / (1.f + expf(-z));
        g_spike[row] = (imp > threshold[0]) ? 1.f : 0.f;
    }
}

// ---------------- fp32 -> bf16 hi/lo split (elementwise) --------------------
__global__ void split_kernel(const float* __restrict__ src,
                             __nv_bfloat16* __restrict__ hi,
                             __nv_bfloat16* __restrict__ lo, int n4) {
    int i = blockIdx.x * blockDim.x + threadIdx.x;
    if (i >= n4) return;
    float4 v = *(const float4*)(src + (size_t)i * 4);
    __nv_bfloat16 h0 = __float2bfloat16(v.x);
    __nv_bfloat16 h1 = __float2bfloat16(v.y);
    __nv_bfloat16 h2 = __float2bfloat16(v.z);
    __nv_bfloat16 h3 = __float2bfloat16(v.w);
    __nv_bfloat16 l0 = __float2bfloat16(v.x - __bfloat162float(h0));
    __nv_bfloat16 l1 = __float2bfloat16(v.y - __bfloat162float(h1));
    __nv_bfloat16 l2 = __float2bfloat16(v.z - __bfloat162float(h2));
    __nv_bfloat16 l3 = __float2bfloat16(v.w - __bfloat162float(h3));
    __nv_bfloat162* hp = (__nv_bfloat162*)(hi + (size_t)i * 4);
    __nv_bfloat162* lp = (__nv_bfloat162*)(lo + (size_t)i * 4);
    hp[0] = __nv_bfloat162(h0, h1); hp[1] = __nv_bfloat162(h2, h3);
    lp[0] = __nv_bfloat162(l0, l1); lp[1] = __nv_bfloat162(l2, l3);
}

// ---------------- W[K,N] -> W^T[N,K] bf16 hi/lo split -----------------------
__global__ void transpose_split_kernel(const float* __restrict__ W,
                                       __nv_bfloat16* __restrict__ Thi,
                                       __nv_bfloat16* __restrict__ Tlo,
                                       int K, int N) {
    __shared__ float tile[32][33];
    int k0 = blockIdx.y * 32, n0 = blockIdx.x * 32;
    int tx = threadIdx.x, ty = threadIdx.y;    // 32 x 8
    #pragma unroll
    for (int j = 0; j < 32; j += 8)
        tile[ty + j][tx] = W[(size_t)(k0 + ty + j) * N + n0 + tx];
    __syncthreads();
    #pragma unroll
    for (int j = 0; j < 32; j += 8) {
        float v = tile[tx][ty + j];
        __nv_bfloat16 h = __float2bfloat16(v);
        __nv_bfloat16 l = __float2bfloat16(v - __bfloat162float(h));
        Thi[(size_t)(n0 + ty + j) * K + k0 + tx] = h;
        Tlo[(size_t)(n0 + ty + j) * K + k0 + tx] = l;
    }
}

// ---------------- mma.sync bf16x3 GEMM (unchanged from R5) ------------------
#define STAGE_B 32768
#define GEMM_SMEM (3 * STAGE_B)
#define TILE_B 8192

__global__ __launch_bounds__(256) void gemm_mma_kernel(
    const __nv_bfloat16* __restrict__ Ahi, const __nv_bfloat16* __restrict__ Alo,
    const __nv_bfloat16* __restrict__ Bhi, const __nv_bfloat16* __restrict__ Blo,
    const float* __restrict__ bias, float* __restrict__ Cmat,
    int M, int N, int K)
{
    extern __shared__ char sm[];
    const uint32_t sbase = smem_u32(sm);

    const int tid  = threadIdx.x;
    const int wid  = tid >> 5;
    const int lane = tid & 31;
    const int m0 = blockIdx.y * 128;
    const int n0 = blockIdx.x * 128;
    const int wm = wid & 1;
    const int wn = wid >> 1;

    const int lr0 = tid >> 2,           lc0 = tid & 3;
    const int lr1 = (tid + 256) >> 2,   lc1 = (tid + 256) & 3;
    const uint32_t so0 = (uint32_t)lr0 * 64 + (uint32_t)((lc0 ^ ((lr0 >> 1) & 3)) * 16);
    const uint32_t so1 = (uint32_t)lr1 * 64 + (uint32_t)((lc1 ^ ((lr1 >> 1) & 3)) * 16);
    const __nv_bfloat16* pAhi0 = Ahi + (size_t)(m0 + lr0) * K + lc0 * 8;
    const __nv_bfloat16* pAhi1 = Ahi + (size_t)(m0 + lr1) * K + lc1 * 8;
    const __nv_bfloat16* pAlo0 = Alo + (size_t)(m0 + lr0) * K + lc0 * 8;
    const __nv_bfloat16* pAlo1 = Alo + (size_t)(m0 + lr1) * K + lc1 * 8;
    const __nv_bfloat16* pBhi0 = Bhi + (size_t)(n0 + lr0) * K + lc0 * 8;
    const __nv_bfloat16* pBhi1 = Bhi + (size_t)(n0 + lr1) * K + lc1 * 8;
    const __nv_bfloat16* pBlo0 = Blo + (size_t)(n0 + lr0) * K + lc0 * 8;
    const __nv_bfloat16* pBlo1 = Blo + (size_t)(n0 + lr1) * K + lc1 * 8;

    float acc[4][4][4];
    #pragma unroll
    for (int i = 0; i < 4; i++)
        #pragma unroll
        for (int j = 0; j < 4; j++)
            #pragma unroll
            for (int c = 0; c < 4; c++) acc[i][j][c] = 0.f;

    const int nch = K >> 5;
    const int lrow = lane & 15;
    const int kc   = lane >> 4;

    #pragma unroll
    for (int s = 0; s < 2; s++) {
        const uint32_t sb = sbase + (uint32_t)s * STAGE_B;
        const int kb = s << 5;
        CP16(sb + 0 * TILE_B + so0, pAhi0 + kb);
        CP16(sb + 0 * TILE_B + so1, pAhi1 + kb);
        CP16(sb + 1 * TILE_B + so0, pAlo0 + kb);
        CP16(sb + 1 * TILE_B + so1, pAlo1 + kb);
        CP16(sb + 2 * TILE_B + so0, pBhi0 + kb);
        CP16(sb + 2 * TILE_B + so1, pBhi1 + kb);
        CP16(sb + 3 * TILE_B + so0, pBlo0 + kb);
        CP16(sb + 3 * TILE_B + so1, pBlo1 + kb);
        CP_COMMIT();
    }

    for (int ch = 0; ch < nch; ch++) {
        CP_WAIT1();
        __syncthreads();

        if (ch + 2 < nch) {
            const uint32_t sb = sbase + (uint32_t)((ch + 2) % 3) * STAGE_B;
            const int kb = (ch + 2) << 5;
            CP16(sb + 0 * TILE_B + so0, pAhi0 + kb);
            CP16(sb + 0 * TILE_B + so1, pAhi1 + kb);
            CP16(sb + 1 * TILE_B + so0, pAlo0 + kb);
            CP16(sb + 1 * TILE_B + so1, pAlo1 + kb);
            CP16(sb + 2 * TILE_B + so0, pBhi0 + kb);
            CP16(sb + 2 * TILE_B + so1, pBhi1 + kb);
            CP16(sb + 3 * TILE_B + so0, pBlo0 + kb);
            CP16(sb + 3 * TILE_B + so1, pBlo1 + kb);
        }
        CP_COMMIT();

        const uint32_t st = sbase + (uint32_t)(ch % 3) * STAGE_B;

        #pragma unroll
        for (int kk = 0; kk < 2; kk++) {
            const int chunk = kk * 2 + kc;
            uint32_t ahi[4][4], alo[4][4];
            #pragma unroll
            for (int mi = 0; mi < 4; mi++) {
                const int r = wm * 64 + mi * 16 + lrow;
                const uint32_t off = (uint32_t)r * 64 +
                    (uint32_t)((chunk ^ ((r >> 1) & 3)) * 16);
                LDSM_X4(ahi[mi][0], ahi[mi][1], ahi[mi][2], ahi[mi][3],
                        st + 0 * TILE_B + off);
                LDSM_X4(alo[mi][0], alo[mi][1], alo[mi][2], alo[mi][3],
                        st + 1 * TILE_B + off);
            }
            uint32_t bhi[2][4], blo[2][4];
            #pragma unroll
            for (int g = 0; g < 2; g++) {
                const int r = wn * 32 + g * 16 + lrow;
                const uint32_t off = (uint32_t)r * 64 +
                    (uint32_t)((chunk ^ ((r >> 1) & 3)) * 16);
                LDSM_X4(bhi[g][0], bhi[g][1], bhi[g][2], bhi[g][3],
                        st + 2 * TILE_B + off);
                LDSM_X4(blo[g][0], blo[g][1], blo[g][2], blo[g][3],
                        st + 3 * TILE_B + off);
            }
            #pragma unroll
            for (int mi = 0; mi < 4; mi++) {
                #pragma unroll
                for (int ni = 0; ni < 4; ni++) {
                    const int g = ni >> 1, o = ni & 1;
                    MMA_BF16(acc[mi][ni], ahi[mi], bhi[g][o], bhi[g][2 + o]);
                    MMA_BF16(acc[mi][ni], ahi[mi], blo[g][o], blo[g][2 + o]);
                    MMA_BF16(acc[mi][ni], alo[mi], bhi[g][o], bhi[g][2 + o]);
                }
            }
        }
    }

    const int orow = lane >> 2;
    const int ocol = (lane & 3) * 2;
    #pragma unroll
    for (int mi = 0; mi < 4; mi++) {
        const int r0 = m0 + wm * 64 + mi * 16 + orow;
        #pragma unroll
        for (int ni = 0; ni < 4; ni++) {
            const int c = n0 + wn * 32 + ni * 8 + ocol;
            const float b0 = bias[c], b1 = bias[c + 1];
            float2 v0 = make_float2(acc[mi][ni][0] + b0, acc[mi][ni][1] + b1);
            float2 v1 = make_float2(acc[mi][ni][2] + b0, acc[mi][ni][3] + b1);
            *(float2*)(Cmat + (size_t)r0 * N + c)       = v0;
            *(float2*)(Cmat + (size_t)(r0 + 8) * N + c) = v1;
        }
    }
}

// ---------------- Lorentz expmap transform -> bf16 hi/lo --------------------
__global__ void transform_kernel() {
    int wid = blockIdx.x * (blockDim.x / 32) + (threadIdx.x >> 5);
    int lane = threadIdx.x & 31;
    int t = wid % T_;
    int h = (wid / T_) % H_;
    int b = wid / (T_ * H_);
    const float* base = g_qkv + ((size_t)(b * T_ + t)) * (3 * C_);
    size_t o = ((size_t)(b * H_ + h) * T_ + t) * D_;

    // Q'
    {
        const float* u = base + 0 * C_ + h * D_;
        float lo = u[lane], hi = u[lane + 32];
        float ss = lo * lo + hi * hi;
        #pragma unroll
        for (int m = 16; m; m >>= 1) ss += __shfl_xor_sync(0xffffffffu, ss, m);
        float u0 = __shfl_sync(0xffffffffu, lo, 0);
        float mink = ss - 2.f * u0 * u0;
        float n = sqrtf(fmaxf(mink, 1e-8f));
        float tme = coshf(n);
        float coef = sinhf(n) / n;
        float v0 = (lane == 0) ? tme : coef * lo;
        float v1 = coef * hi;
        __nv_bfloat16 h0 = __float2bfloat16(v0);
        __nv_bfloat16 h1 = __float2bfloat16(v1);
        g_Qhi[o + lane] = h0;       g_Qhi[o + lane + 32] = h1;
        g_Qlo[o + lane] = __float2bfloat16(v0 - __bfloat162float(h0));
        g_Qlo[o + lane + 32] = __float2bfloat16(v1 - __bfloat162float(h1));
    }
    // K' (space negated)
    {
        const float* u = base + 1 * C_ + h * D_;
        float lo = u[lane], hi = u[lane + 32];
        float ss = lo * lo + hi * hi;
        #pragma unroll
        for (int m = 16; m; m >>= 1) ss += __shfl_xor_sync(0xffffffffu, ss, m);
        float u0 = __shfl_sync(0xffffffffu, lo, 0);
        float mink = ss - 2.f * u0 * u0;
        float n = sqrtf(fmaxf(mink, 1e-8f));
        float tme = coshf(n);
        float coef = sinhf(n) / n;
        float v0 = (lane == 0) ? tme : -coef * lo;
        float v1 = -coef * hi;
        __nv_bfloat16 h0 = __float2bfloat16(v0);
        __nv_bfloat16 h1 = __float2bfloat16(v1);
        g_Khi[o + lane] = h0;       g_Khi[o + lane + 32] = h1;
        g_Klo[o + lane] = __float2bfloat16(v0 - __bfloat162float(h0));
        g_Klo[o + lane + 32] = __float2bfloat16(v1 - __bfloat162float(h1));
    }
    // V
    {
        const float* u = base + 2 * C_ + h * D_;
        float v0 = u[lane], v1 = u[lane + 32];
        __nv_bfloat16 h0 = __float2bfloat16(v0);
        __nv_bfloat16 h1 = __float2bfloat16(v1);
        g_Vhi[o + lane] = h0;       g_Vhi[o + lane + 32] = h1;
        g_Vlo[o + lane] = __float2bfloat16(v0 - __bfloat162float(h0));
        g_Vlo[o + lane + 32] = __float2bfloat16(v1 - __bfloat162float(h1));
    }
}

// ---------------- tensor-core flash attention (bf16x3) ----------------------
// CTA: 64 q-rows, 4 warps (16 rows each); j tiles of 64, double-buffered K/V.
// smem: Qhi@0 Qlo@8K | buf0: Khi@16K Klo@24K Vhi@32K Vlo@40K | buf1: +32K
#define AT_SMEM 81920
#define SWO(row, ch) ((uint32_t)(row) * 128u + (uint32_t)(((ch) ^ (((row) >> 1) & 3)) * 16))

__global__ __launch_bounds__(128) void attn_kernel() {
    extern __shared__ char sm[];
    const uint32_t sb = smem_u32(sm);
    const int tid = threadIdx.x;
    const int wid = tid >> 5;
    const int lane = tid & 31;
    const int ti = blockIdx.x;
    const int h  = blockIdx.y;
    const int b  = blockIdx.z;
    const int bh = b * H_ + h;
    const int i0 = ti * 64;
    const size_t gb = (size_t)bh * T_ * D_;

    const int lrow  = lane & 15;
    const int khalf = lane >> 4;

    // ---- prologue: Q tile + K/V tile 0 in one cp.async group ----
    #pragma unroll
    for (int i = 0; i < 8; i++) {
        const int arr = i >> 2;
        const int sub = tid + (i & 3) * 128;
        const int row = sub >> 3, ch = sub & 7;
        const __nv_bfloat16* g = arr ? g_Qlo : g_Qhi;
        CP16(sb + (uint32_t)arr * 8192u + SWO(row, ch),
             g + gb + (size_t)(i0 + row) * D_ + ch * 8);
    }
    #pragma unroll
    for (int i = 0; i < 16; i++) {
        const int arr = i >> 2;
        const int sub = tid + (i & 3) * 128;
        const int row = sub >> 3, ch = sub & 7;
        const __nv_bfloat16* g = (arr == 0) ? g_Khi : (arr == 1) ? g_Klo
                               : (arr == 2) ? g_Vhi : g_Vlo;
        CP16(sb + 16384u + (uint32_t)arr * 8192u + SWO(row, ch),
             g + gb + (size_t)row * D_ + ch * 8);
    }
    CP_COMMIT();

    float O[8][4];
    #pragma unroll
    for (int i = 0; i < 8; i++)
        #pragma unroll
        for (int c = 0; c < 4; c++) O[i][c] = 0.f;
    float m0 = -1e30f, m1 = -1e30f, l0 = 0.f, l1 = 0.f;
    uint32_t ahi[4][4], alo[4][4];

    const int rq = lane >> 2;            // row-in-8
    const int cq = (lane & 3) * 2;       // col pair base
    const int grow0 = i0 + wid * 16 + rq;
    const int grow1 = grow0 + 8;

    for (int tj = 0; tj <= ti; tj++) {
        // prefetch next K/V tile into the other buffer
        if (tj < ti) {
            const uint32_t dst = sb + 16384u + (uint32_t)((tj + 1) & 1) * 32768u;
            const size_t src = gb + (size_t)(tj + 1) * 64 * D_;
            #pragma unroll
            for (int i = 0; i < 16; i++) {
                const int arr = i >> 2;
                const int sub = tid + (i & 3) * 128;
                const int row = sub >> 3, ch = sub & 7;
                const __nv_bfloat16* g = (arr == 0) ? g_Khi : (arr == 1) ? g_Klo
                                       : (arr == 2) ? g_Vhi : g_Vlo;
                CP16(dst + (uint32_t)arr * 8192u + SWO(row, ch),
                     g + src + (size_t)row * D_ + ch * 8);
            }
        }
        CP_COMMIT();
        CP_WAIT1();
        __syncthreads();

        if (tj == 0) {  // Q A-frags, cached for all tiles
            #pragma unroll
            for (int kc = 0; kc < 4; kc++) {
                const int r = wid * 16 + lrow;
                const uint32_t off = SWO(r, kc * 2 + khalf);
                LDSM_X4(ahi[kc][0], ahi[kc][1], ahi[kc][2], ahi[kc][3], sb + off);
                LDSM_X4(alo[kc][0], alo[kc][1], alo[kc][2], alo[kc][3],
                        sb + 8192u + off);
            }
        }

        const uint32_t kbuf = sb + 16384u + (uint32_t)(tj & 1) * 32768u;

        // ---- S = Q' K'^T (bf16x3) ----
        float acc[8][4];
        #pragma unroll
        for (int i = 0; i < 8; i++)
            #pragma unroll
            for (int c = 0; c < 4; c++) acc[i][c] = 0.f;

        #pragma unroll
        for (int kc = 0; kc < 4; kc++) {
            uint32_t bh4[4][4], bl4[4][4];
            #pragma unroll
            for (int g = 0; g < 4; g++) {
                const int r = g * 16 + lrow;
                const uint32_t off = SWO(r, kc * 2 + khalf);
                LDSM_X4(bh4[g][0], bh4[g][1], bh4[g][2], bh4[g][3], kbuf + off);
                LDSM_X4(bl4[g][0], bl4[g][1], bl4[g][2], bl4[g][3],
                        kbuf + 8192u + off);
            }
            #pragma unroll
            for (int ni = 0; ni < 8; ni++) {
                const int g = ni >> 1, o = ni & 1;
                MMA_BF16(acc[ni], ahi[kc], bh4[g][o], bh4[g][2 + o]);
                MMA_BF16(acc[ni], ahi[kc], bl4[g][o], bl4[g][2 + o]);
                MMA_BF16(acc[ni], alo[kc], bh4[g][o], bh4[g][2 + o]);
            }
        }

        // ---- Lorentz transform + causal mask ----
        const int j0 = tj * 64;
        #pragma unroll
        for (int ni = 0; ni < 8; ni++) {
            #pragma unroll
            for (int c = 0; c < 4; c++) {
                const int col = j0 + ni * 8 + cq + (c & 1);
                const int grow = (c < 2) ? grow0 : grow1;
                float x = fmaxf(acc[ni][c], 1.0f + 1e-7f);
                float dd = __logf(x + sqrtf(fmaxf(x * x - 1.f, 0.f)));
                float s = -dd * dd * 0.125f;
                acc[ni][c] = (col > grow) ? -1e30f : s;
            }
        }

        // ---- online softmax (rows grow0 / grow1, quad = 4 lanes) ----
        {
            float mx = -1e30f;
            #pragma unroll
            for (int ni = 0; ni < 8; ni++)
                mx = fmaxf(mx, fmaxf(acc[ni][0], acc[ni][1]));
            mx = fmaxf(mx, __shfl_xor_sync(0xffffffffu, mx, 1));
            mx = fmaxf(mx, __shfl_xor_sync(0xffffffffu, mx, 2));
            float mnew = fmaxf(m0, mx);
            float es = __expf(m0 - mnew);
            l0 *= es;
            #pragma unroll
            for (int ni = 0; ni < 8; ni++) { O[ni][0] *= es; O[ni][1] *= es; }
            float rs = 0.f;
            #pragma unroll
            for (int ni = 0; ni < 8; ni++) {
                float p0 = __expf(acc[ni][0] - mnew);
                float p1 = __expf(acc[ni][1] - mnew);
                acc[ni][0] = p0; acc[ni][1] = p1; rs += p0 + p1;
            }
            rs += __shfl_xor_sync(0xffffffffu, rs, 1);
            rs += __shfl_xor_sync(0xffffffffu, rs, 2);
            l0 += rs; m0 = mnew;
        }
        {
            float mx = -1e30f;
            #pragma unroll
            for (int ni = 0; ni < 8; ni++)
                mx = fmaxf(mx, fmaxf(acc[ni][2], acc[ni][3]));
            mx = fmaxf(mx, __shfl_xor_sync(0xffffffffu, mx, 1));
            mx = fmaxf(mx, __shfl_xor_sync(0xffffffffu, mx, 2));
            float mnew = fmaxf(m1, mx);
            float es = __expf(m1 - mnew);
            l1 *= es;
            #pragma unroll
            for (int ni = 0; ni < 8; ni++) { O[ni][2] *= es; O[ni][3] *= es; }
            float rs = 0.f;
            #pragma unroll
            for (int ni = 0; ni < 8; ni++) {
                float p0 = __expf(acc[ni][2] - mnew);
                float p1 = __expf(acc[ni][3] - mnew);
                acc[ni][2] = p0; acc[ni][3] = p1; rs += p0 + p1;
            }
            rs += __shfl_xor_sync(0xffffffffu, rs, 1);
            rs += __shfl_xor_sync(0xffffffffu, rs, 2);
            l1 += rs; m1 = mnew;
        }

        // ---- PV: O += P V (bf16x3, P packed in registers) ----
        const uint32_t vbuf = kbuf + 16384u;
        #pragma unroll
        for (int kc = 0; kc < 4; kc++) {
            uint32_t ph[4], pl[4];
            #pragma unroll
            for (int q = 0; q < 4; q++) {
                const int ni = 2 * kc + (q >> 1);
                const int c0 = (q & 1) * 2;
                float a = acc[ni][c0], bb = acc[ni][c0 + 1];
                uint32_t hp = pack_bf16(a, bb);
                __nv_bfloat162 hv = *(__nv_bfloat162*)&hp;
                pl[(q >> 1) * 1 + (q & 1) * 2] = 0; // placeholder (overwritten)
                // A-frag order: a0=(r,k0-7) a1=(r+8,k0-7) a2=(r,k8-15) a3=(r+8,k8-15)
                const int idx = (q & 1) + (q >> 1) * 2;   // q0->a0,q1->a1,q2->a2,q3->a3
                ph[idx] = hp;
                pl[idx] = pack_bf16(a - __low2float(hv), bb - __high2float(hv));
            }
            #pragma unroll
            for (int g = 0; g < 4; g++) {
                const int r = kc * 16 + ((lane >> 3) & 1) * 8 + (lane & 7);
                const uint32_t off = SWO(r, g * 2 + khalf);
                uint32_t vh[4], vl[4];
                LDSM_X4_T(vh[0], vh[1], vh[2], vh[3], vbuf + off);
                LDSM_X4_T(vl[0], vl[1], vl[2], vl[3], vbuf + 8192u + off);
                MMA_BF16(O[g * 2],     ph, vh[0], vh[1]);
                MMA_BF16(O[g * 2],     ph, vl[0], vl[1]);
                MMA_BF16(O[g * 2],     pl, vh[0], vh[1]);
                MMA_BF16(O[g * 2 + 1], ph, vh[2], vh[3]);
                MMA_BF16(O[g * 2 + 1], ph, vl[2], vl[3]);
                MMA_BF16(O[g * 2 + 1], pl, vh[2], vh[3]);
            }
        }
        __syncthreads();   // done with this buffer before reuse
    }

    // ---- epilogue ----
    const float inv0 = g_spike[b * T_ + grow0] / l0;
    const float inv1 = g_spike[b * T_ + grow1] / l1;
    float* y0 = g_Y + ((size_t)(b * T_ + grow0)) * C_ + h * D_;
    float* y1 = g_Y + ((size_t)(b * T_ + grow1)) * C_ + h * D_;
    #pragma unroll
    for (int ni = 0; ni < 8; ni++) {
        const int d = ni * 8 + cq;
        *(float2*)(y0 + d) = make_float2(O[ni][0] * inv0, O[ni][1] * inv0);
        *(float2*)(y1 + d) = make_float2(O[ni][2] * inv1, O[ni][3] * inv1);
    }
}

// ---------------- launch -----------------------------------------------------
extern "C" void kernel_launch(void* const* d_in, const int* in_sizes, int n_in,
                              void* d_out, int out_size) {
    const float* x      = (const float*)d_in[0];
    const float* W_qkv  = (const float*)d_in[1];
    const float* b_qkv  = (const float*)d_in[2];
    const float* W_out  = (const float*)d_in[3];
    const float* b_out  = (const float*)d_in[4];
    const float* w_sur  = (const float*)d_in[5];
    const float* b_sur  = (const float*)d_in[6];
    const float* thresh = (const float*)d_in[7];
    float* out = (float*)d_out;

    float *p_qkv, *p_Y;
    __nv_bfloat16 *p_xhi, *p_xlo, *p_Wqt_hi, *p_Wqt_lo;
    __nv_bfloat16 *p_Yhi, *p_Ylo, *p_Wot_hi, *p_Wot_lo;
    cudaGetSymbolAddress((void**)&p_qkv, g_qkv);
    cudaGetSymbolAddress((void**)&p_Y,   g_Y);
    cudaGetSymbolAddress((void**)&p_xhi, g_xhi);
    cudaGetSymbolAddress((void**)&p_xlo, g_xlo);
    cudaGetSymbolAddress((void**)&p_Wqt_hi, g_Wqt_hi);
    cudaGetSymbolAddress((void**)&p_Wqt_lo, g_Wqt_lo);
    cudaGetSymbolAddress((void**)&p_Yhi, g_Yhi);
    cudaGetSymbolAddress((void**)&p_Ylo, g_Ylo);
    cudaGetSymbolAddress((void**)&p_Wot_hi, g_Wot_hi);
    cudaGetSymbolAddress((void**)&p_Wot_lo, g_Wot_lo);

    cudaFuncSetAttribute(attn_kernel,
                         cudaFuncAttributeMaxDynamicSharedMemorySize, AT_SMEM);
    cudaFuncSetAttribute(gemm_mma_kernel,
                         cudaFuncAttributeMaxDynamicSharedMemorySize, GEMM_SMEM);

    const int M = B_ * T_;   // 4096

    // 1. spike gate
    spike_kernel<<<M / 8, 256>>>(x, w_sur, b_sur, thresh);

    // 2. operand prep for QKV GEMM
    split_kernel<<<(M * C_ / 4 + 255) / 256, 256>>>(x, p_xhi, p_xlo, M * C_ / 4);
    transpose_split_kernel<<<dim3(3 * C_ / 32, C_ / 32), dim3(32, 8)>>>(
        W_qkv, p_Wqt_hi, p_Wqt_lo, C_, 3 * C_);

    // 3. QKV GEMM
    gemm_mma_kernel<<<dim3(3 * C_ / 128, M / 128), 256, GEMM_SMEM>>>(
        p_xhi, p_xlo, p_Wqt_hi, p_Wqt_lo, b_qkv, p_qkv, M, 3 * C_, C_);

    // 4. Lorentz transform -> bf16 hi/lo Q',K',V
    transform_kernel<<<(B_ * H_ * T_) / 8, 256>>>();

    // 5. tensor-core flash attention
    attn_kernel<<<dim3(T_ / 64, H_, B_), 128, AT_SMEM>>>();

    // 6. operand prep + out projection
    split_kernel<<<(M * C_ / 4 + 255) / 256, 256>>>(p_Y, p_Yhi, p_Ylo, M * C_ / 4);
    transpose_split_kernel<<<dim3(C_ / 32, C_ / 32), dim3(32, 8)>>>(
        W_out, p_Wot_hi, p_Wot_lo, C_, C_);
    gemm_mma_kernel<<<dim3(C_ / 128, M / 128), 256, GEMM_SMEM>>>(
        p_Yhi, p_Ylo, p_Wot_hi, p_Wot_lo, b_out, out, M, C_, C_);
}